// round 5
// baseline (speedup 1.0000x reference)
#include <cuda_runtime.h>
#include <cuda_bf16.h>
#include <cstdint>

// ---------------------------------------------------------------------------
// Problem constants: B=8, S=512, D_MODEL=1024, H=16, DK=DV=64, BH=128
// ---------------------------------------------------------------------------
#define BB   8
#define SS_  512
#define DM   1024
#define HH   16
#define DKV  64
#define BH   128
#define SCALE 0.125f

// ---------------------------------------------------------------------------
// Scratch (device globals)
// ---------------------------------------------------------------------------
__device__ float g_sc [(size_t)BH * SS_ * SS_];    // scores fp32 [bh,i,j]
__device__ float g_ctx[(size_t)BB * SS_ * DM];     // context fp32

// int8 projection staging
// A8 row: [I1(1024) | I1(1024) | I2(1024)] bytes
// B8 row: [J1(1024) | J2(1024) | J1(1024)] bytes  (row = output col n)
__device__ __align__(16) uint8_t g_A8   [(size_t)4096 * 3072];
__device__ __align__(16) uint8_t g_Actx8[(size_t)4096 * 3072];
__device__ __align__(16) uint8_t g_Bqkv8[(size_t)3072 * 3072];
__device__ __align__(16) uint8_t g_Bo8  [(size_t)1024 * 3072];

// abs-max scales (bit-pattern for atomicMax on non-negative floats)
// slots: 0=queries, 1=Wq, 2=Wk, 3=Wv, 4=Wo, 5=ctx
__device__ unsigned g_amax_bits[8];

// attention operand splits (hi/lo bf16)
__device__ __align__(16) __nv_bfloat16 qh [(size_t)BH * SS_ * DKV];
__device__ __align__(16) __nv_bfloat16 ql [(size_t)BH * SS_ * DKV];
__device__ __align__(16) __nv_bfloat16 kh [(size_t)BH * SS_ * DKV];
__device__ __align__(16) __nv_bfloat16 kl [(size_t)BH * SS_ * DKV];
__device__ __align__(16) __nv_bfloat16 vth[(size_t)BH * DKV * SS_];  // [bh,d,s]
__device__ __align__(16) __nv_bfloat16 vtl[(size_t)BH * DKV * SS_];
__device__ __align__(16) __nv_bfloat16 ekh [(size_t)SS_ * SS_ * DKV]; // [i,j,d]
__device__ __align__(16) __nv_bfloat16 ekl [(size_t)SS_ * SS_ * DKV];
__device__ __align__(16) __nv_bfloat16 evth[(size_t)SS_ * DKV * SS_]; // [i,d,j]
__device__ __align__(16) __nv_bfloat16 evtl[(size_t)SS_ * DKV * SS_];
__device__ __align__(16) __nv_bfloat16 wh [(size_t)BH * SS_ * SS_];   // [bh,i,j]
__device__ __align__(16) __nv_bfloat16 wl [(size_t)BH * SS_ * SS_];

__device__ __forceinline__ uint32_t s2u(const void* p) {
    uint32_t a;
    asm("{ .reg .u64 t; cvta.to.shared.u64 t, %1; cvt.u32.u64 %0, t; }"
        : "=r"(a) : "l"(p));
    return a;
}
__device__ __forceinline__ uint32_t pk2(__nv_bfloat16 a, __nv_bfloat16 b) {
    return (uint32_t)__bfloat16_as_ushort(a) | ((uint32_t)__bfloat16_as_ushort(b) << 16);
}
__device__ __forceinline__ uint32_t pkb(int a, int b, int c, int d) {
    return (uint32_t)(a & 255) | ((uint32_t)(b & 255) << 8) |
           ((uint32_t)(c & 255) << 16) | ((uint32_t)(d & 255) << 24);
}

#define CP_ASYNC16(dst, src) \
    asm volatile("cp.async.cg.shared.global [%0], [%1], 16;" :: "r"(dst), "l"(src) : "memory")
#define CP_COMMIT() asm volatile("cp.async.commit_group;" ::: "memory")
#define CP_WAIT0()  asm volatile("cp.async.wait_group 0;" ::: "memory")

#define LDMATX4(r0, r1, r2, r3, addr) \
    asm volatile("ldmatrix.sync.aligned.m8n8.x4.shared.b16 {%0,%1,%2,%3}, [%4];" \
        : "=r"(r0), "=r"(r1), "=r"(r2), "=r"(r3) : "r"(addr))

#define MMA16816(c, a, b) \
    asm volatile("mma.sync.aligned.m16n8k16.row.col.f32.bf16.bf16.f32 " \
        "{%0,%1,%2,%3}, {%4,%5,%6,%7}, {%8,%9}, {%0,%1,%2,%3};" \
        : "+f"((c)[0]), "+f"((c)[1]), "+f"((c)[2]), "+f"((c)[3]) \
        : "r"((a)[0]), "r"((a)[1]), "r"((a)[2]), "r"((a)[3]), \
          "r"((b)[0]), "r"((b)[1]))

#define MMA_S8(c, a, b) \
    asm volatile("mma.sync.aligned.m16n8k32.row.col.s32.s8.s8.s32 " \
        "{%0,%1,%2,%3}, {%4,%5,%6,%7}, {%8,%9}, {%0,%1,%2,%3};" \
        : "+r"((c)[0]), "+r"((c)[1]), "+r"((c)[2]), "+r"((c)[3]) \
        : "r"((a)[0]), "r"((a)[1]), "r"((a)[2]), "r"((a)[3]), \
          "r"((b)[0]), "r"((b)[1]))

#define LDS_   40                 // padded row stride: 40 b16 units = 80 bytes
#define TILEB  (128 * LDS_ * 2)   // 10240 bytes

// ===========================================================================
// abs-max reduction (slot-indexed); src==nullptr means g_ctx
// ===========================================================================
__global__ void k_amax_init() { if (threadIdx.x < 8) g_amax_bits[threadIdx.x] = 0; }

__global__ __launch_bounds__(256) void k_amax(const float* __restrict__ src, int n, int slot)
{
    if (!src) src = (const float*)g_ctx;
    float m = 0.f;
    for (int i = blockIdx.x * 256 + threadIdx.x; i < (n >> 2); i += gridDim.x * 256) {
        float4 v = ((const float4*)src)[i];
        m = fmaxf(m, fmaxf(fmaxf(fabsf(v.x), fabsf(v.y)), fmaxf(fabsf(v.z), fabsf(v.w))));
    }
#pragma unroll
    for (int o = 16; o > 0; o >>= 1) m = fmaxf(m, __shfl_xor_sync(~0u, m, o));
    if ((threadIdx.x & 31) == 0)
        atomicMax(&g_amax_bits[slot], __float_as_uint(m));
}

// ===========================================================================
// int8 quantize X: fp32 [4096,1024] -> [4096 rows][I1|I1|I2] bytes
// which=0: queries (slot 0) -> g_A8 ; which=1: g_ctx (slot 5) -> g_Actx8
// ===========================================================================
__global__ __launch_bounds__(256) void k_quant_x(const float* __restrict__ src_in, int which)
{
    const float* src = which ? (const float*)g_ctx : src_in;
    uint8_t* dst = which ? g_Actx8 : g_A8;
    const float s = 127.f / fmaxf(__uint_as_float(g_amax_bits[which ? 5 : 0]), 1e-20f);

    int idx = blockIdx.x * 256 + threadIdx.x;
    int r = idx >> 7;
    int c0 = (idx & 127) << 3;
    const float* p = src + (size_t)r * 1024 + c0;
    float4 v0 = *(const float4*)(p);
    float4 v1 = *(const float4*)(p + 4);
    float f[8] = {v0.x, v0.y, v0.z, v0.w, v1.x, v1.y, v1.z, v1.w};
    int i1[8], i2[8];
#pragma unroll
    for (int j = 0; j < 8; j++) {
        float xs = f[j] * s;
        i1[j] = __float2int_rn(xs);
        int t = __float2int_rn((xs - (float)i1[j]) * 256.f);
        i2[j] = min(127, max(-127, t));
    }
    uint2 P1 = make_uint2(pkb(i1[0], i1[1], i1[2], i1[3]), pkb(i1[4], i1[5], i1[6], i1[7]));
    uint2 P2 = make_uint2(pkb(i2[0], i2[1], i2[2], i2[3]), pkb(i2[4], i2[5], i2[6], i2[7]));
    uint8_t* row = dst + (size_t)r * 3072;
    *(uint2*)(row + c0)        = P1;
    *(uint2*)(row + 1024 + c0) = P1;
    *(uint2*)(row + 2048 + c0) = P2;
}

// ===========================================================================
// int8 quantize+transpose weights: W[1024k,1024n] -> B8[n][J1|J2|J1]
// ===========================================================================
__global__ __launch_bounds__(256) void k_quant_w(
    const float* __restrict__ W0, const float* __restrict__ W1,
    const float* __restrict__ W2, const float* __restrict__ W3)
{
    const int slot = blockIdx.z;
    const float* W = (slot == 0) ? W0 : (slot == 1) ? W1 : (slot == 2) ? W2 : W3;
    uint8_t* dst = (slot < 3) ? (g_Bqkv8 + (size_t)slot * 1024 * 3072) : g_Bo8;
    const float s = 127.f / fmaxf(__uint_as_float(g_amax_bits[1 + slot]), 1e-20f);

    int nl = blockIdx.x * 256 + threadIdx.x;
    int k0 = blockIdx.y << 3;
    int i1[8], i2[8];
#pragma unroll
    for (int j = 0; j < 8; j++) {
        float xs = W[(size_t)(k0 + j) * 1024 + nl] * s;
        i1[j] = __float2int_rn(xs);
        int t = __float2int_rn((xs - (float)i1[j]) * 256.f);
        i2[j] = min(127, max(-127, t));
    }
    uint2 P1 = make_uint2(pkb(i1[0], i1[1], i1[2], i1[3]), pkb(i1[4], i1[5], i1[6], i1[7]));
    uint2 P2 = make_uint2(pkb(i2[0], i2[1], i2[2], i2[3]), pkb(i2[4], i2[5], i2[6], i2[7]));
    uint8_t* row = dst + (size_t)nl * 3072;
    *(uint2*)(row + k0)        = P1;
    *(uint2*)(row + 1024 + k0) = P2;
    *(uint2*)(row + 2048 + k0) = P1;
}

// ===========================================================================
// EK split: fp32 [i,j,64] -> ekh/ekl bf16 (elementwise)
// ===========================================================================
__global__ __launch_bounds__(256) void k_split_ek(const float* __restrict__ EK)
{
    size_t base = ((size_t)blockIdx.x * 256 + threadIdx.x) * 8;
    float4 v0 = *(const float4*)(EK + base);
    float4 v1 = *(const float4*)(EK + base + 4);
    float f[8] = {v0.x, v0.y, v0.z, v0.w, v1.x, v1.y, v1.z, v1.w};
    uint4 H, L;
    uint32_t hu[4], lu[4];
#pragma unroll
    for (int i = 0; i < 4; i++) {
        __nv_bfloat16 h0 = __float2bfloat16(f[2*i]);
        __nv_bfloat16 h1 = __float2bfloat16(f[2*i+1]);
        __nv_bfloat16 l0 = __float2bfloat16(f[2*i]   - __bfloat162float(h0));
        __nv_bfloat16 l1 = __float2bfloat16(f[2*i+1] - __bfloat162float(h1));
        hu[i] = pk2(h0, h1); lu[i] = pk2(l0, l1);
    }
    H.x = hu[0]; H.y = hu[1]; H.z = hu[2]; H.w = hu[3];
    L.x = lu[0]; L.y = lu[1]; L.z = lu[2]; L.w = lu[3];
    *(uint4*)(ekh + base) = H;
    *(uint4*)(ekl + base) = L;
}

// ===========================================================================
// EV transpose-split: fp32 [i,j,64] -> evth/evtl bf16 [i,64,512]
// ===========================================================================
__global__ __launch_bounds__(256) void k_split_evt(const float* __restrict__ EV)
{
    __shared__ float ts[32][33];
    const int jt = blockIdx.x, dt = blockIdx.y, i = blockIdx.z;
    const int t = threadIdx.x;
    const int r = t >> 3, c0 = (t & 7) << 2;

    float4 v = *(const float4*)(EV + ((size_t)(i * SS_ + jt * 32 + r)) * DKV + dt * 32 + c0);
    ts[r][c0 + 0] = v.x; ts[r][c0 + 1] = v.y;
    ts[r][c0 + 2] = v.z; ts[r][c0 + 3] = v.w;
    __syncthreads();

    uint32_t hu[2], lu[2];
#pragma unroll
    for (int p = 0; p < 2; p++) {
        float f0 = ts[c0 + 2*p][r];
        float f1 = ts[c0 + 2*p + 1][r];
        __nv_bfloat16 h0 = __float2bfloat16(f0);
        __nv_bfloat16 h1 = __float2bfloat16(f1);
        __nv_bfloat16 l0 = __float2bfloat16(f0 - __bfloat162float(h0));
        __nv_bfloat16 l1 = __float2bfloat16(f1 - __bfloat162float(h1));
        hu[p] = pk2(h0, h1); lu[p] = pk2(l0, l1);
    }
    size_t off = ((size_t)i * DKV + dt * 32 + r) * SS_ + jt * 32 + c0;
    *(uint2*)(evth + off) = make_uint2(hu[0], hu[1]);
    *(uint2*)(evtl + off) = make_uint2(lu[0], lu[1]);
}

// ===========================================================================
// int8 IMMA GEMM (projections): C[4096,N] = A8 @ B8^T with 2-phase scaling
//   chunks 0-15:  I1@J1            (scale 1)      -> acc  (moved to accf)
//   chunks 16-47: I1@J2 + I2@J1    (scale 1/256)  -> acc
//   out = sx*sw*(accf + acc/256) + bias
// mode 0: QKV -> q/k splits + transposed-v splits; mode 1: OUT -> outp
// ===========================================================================
#define NCHUNK8 48

__global__ __launch_bounds__(256) void k_gemm_s8(
    const float* __restrict__ b0p, const float* __restrict__ b1p,
    const float* __restrict__ b2p, float* __restrict__ outp, int mode)
{
    __shared__ __align__(16) char smem[2 * 2 * TILEB];

    const int tid  = threadIdx.x;
    const int wid  = tid >> 5, lane = tid & 31;
    const int wm   = wid >> 2, wn = wid & 3;
    const int m0   = blockIdx.y * 128, n0 = blockIdx.x * 128;
    const uint32_t sbase = s2u(smem);

    const uint8_t* __restrict__ Ag = mode ? g_Actx8 : g_A8;
    const uint8_t* __restrict__ Bg = mode ? g_Bo8   : g_Bqkv8;

    const int lrow0 = tid >> 2;
    const int lsegB = (tid & 3) << 4;   // byte offset 0/16/32/48 within 64B chunk

    int   acc [4][4][4];
    float accf[4][4][4];
#pragma unroll
    for (int i = 0; i < 4; i++)
#pragma unroll
        for (int j = 0; j < 4; j++)
#pragma unroll
            for (int q = 0; q < 4; q++) { acc[i][j][q] = 0; accf[i][j][q] = 0.f; }

    {
        uint32_t dA = sbase, dB = sbase + TILEB;
#pragma unroll
        for (int u = 0; u < 2; u++) {
            int row = lrow0 + u * 64;
            CP_ASYNC16(dA + row * 80 + lsegB, Ag + (size_t)(m0 + row) * 3072 + lsegB);
            CP_ASYNC16(dB + row * 80 + lsegB, Bg + (size_t)(n0 + row) * 3072 + lsegB);
        }
        CP_COMMIT();
    }

    for (int c = 0; c < NCHUNK8; c++) {
        CP_WAIT0();
        __syncthreads();

        if (c + 1 < NCHUNK8) {
            uint32_t dA = sbase + ((c + 1) & 1) * 2 * TILEB;
            uint32_t dB = dA + TILEB;
            const int koff = (c + 1) * 64 + lsegB;
#pragma unroll
            for (int u = 0; u < 2; u++) {
                int row = lrow0 + u * 64;
                CP_ASYNC16(dA + row * 80 + lsegB, Ag + (size_t)(m0 + row) * 3072 + koff);
                CP_ASYNC16(dB + row * 80 + lsegB, Bg + (size_t)(n0 + row) * 3072 + koff);
            }
            CP_COMMIT();
        }

        const uint32_t bufA = sbase + (c & 1) * 2 * TILEB;
        const uint32_t bufB = bufA + TILEB;
        const int lr = lane & 15, lc2 = ((lane >> 4) << 3) * 2;  // byte col 0/16

#pragma unroll
        for (int ks = 0; ks < 2; ks++) {
            uint32_t a[4][4];
#pragma unroll
            for (int mi = 0; mi < 4; mi++) {
                uint32_t addr = bufA + (wm * 64 + mi * 16 + lr) * 80 + ks * 32 + lc2;
                LDMATX4(a[mi][0], a[mi][1], a[mi][2], a[mi][3], addr);
            }
            uint32_t b[4][2];
#pragma unroll
            for (int ni2 = 0; ni2 < 2; ni2++) {
                uint32_t r0, r1, r2, r3;
                uint32_t addr = bufB + (wn * 32 + ni2 * 16 + lr) * 80 + ks * 32 + lc2;
                LDMATX4(r0, r1, r2, r3, addr);
                b[2 * ni2][0] = r0;     b[2 * ni2][1] = r2;
                b[2 * ni2 + 1][0] = r1; b[2 * ni2 + 1][1] = r3;
            }
#pragma unroll
            for (int mi = 0; mi < 4; mi++)
#pragma unroll
                for (int ni = 0; ni < 4; ni++)
                    MMA_S8(acc[mi][ni], a[mi], b[ni]);
        }

        if (c == 15) {   // end of phase 1 (I1@J1)
#pragma unroll
            for (int i = 0; i < 4; i++)
#pragma unroll
                for (int j = 0; j < 4; j++)
#pragma unroll
                    for (int q = 0; q < 4; q++) {
                        accf[i][j][q] = (float)acc[i][j][q];
                        acc[i][j][q] = 0;
                    }
        }
        __syncthreads();
    }

    // -------- epilogue --------
    const int g  = lane >> 2;
    const int tc = (lane & 3) << 1;

    float sx, sw;
    int proj = 0;
    if (mode == 0) {
        proj = n0 >> 10;
        sx = __uint_as_float(g_amax_bits[0]);
        sw = __uint_as_float(g_amax_bits[1 + proj]);
    } else {
        sx = __uint_as_float(g_amax_bits[5]);
        sw = __uint_as_float(g_amax_bits[4]);
    }
    const float scf = (sx / 127.f) * (sw / 127.f);

    if (mode == 0) {
        const float* bias = (proj == 0) ? b0p : (proj == 1) ? b1p : b2p;
#pragma unroll
        for (int mi = 0; mi < 4; mi++) {
            int m = m0 + wm * 64 + mi * 16 + g;
            int b_ = m >> 9, s_ = m & 511;
            int s2 = s_ + 8;
#pragma unroll
            for (int ni = 0; ni < 4; ni++) {
                int nl = (n0 & 1023) + wn * 32 + ni * 8 + tc;
                int hd = nl >> 6, d = nl & 63;
                int bh_ = b_ * HH + hd;
                float x0 = scf * (accf[mi][ni][0] + (float)acc[mi][ni][0] * (1.f/256.f)) + bias[nl];
                float x1 = scf * (accf[mi][ni][1] + (float)acc[mi][ni][1] * (1.f/256.f)) + bias[nl + 1];
                float x2 = scf * (accf[mi][ni][2] + (float)acc[mi][ni][2] * (1.f/256.f)) + bias[nl];
                float x3 = scf * (accf[mi][ni][3] + (float)acc[mi][ni][3] * (1.f/256.f)) + bias[nl + 1];
                __nv_bfloat16 hb0 = __float2bfloat16(x0), lb0 = __float2bfloat16(x0 - __bfloat162float(hb0));
                __nv_bfloat16 hb1 = __float2bfloat16(x1), lb1 = __float2bfloat16(x1 - __bfloat162float(hb1));
                __nv_bfloat16 hb2 = __float2bfloat16(x2), lb2 = __float2bfloat16(x2 - __bfloat162float(hb2));
                __nv_bfloat16 hb3 = __float2bfloat16(x3), lb3 = __float2bfloat16(x3 - __bfloat162float(hb3));
                if (proj < 2) {
                    __nv_bfloat16* ah = (proj == 0) ? qh : kh;
                    __nv_bfloat16* al = (proj == 0) ? ql : kl;
                    size_t o0 = ((size_t)bh_ * SS_ + s_) * DKV + d;
                    size_t o1 = o0 + 8 * DKV;
                    *(uint32_t*)(ah + o0) = pk2(hb0, hb1);
                    *(uint32_t*)(al + o0) = pk2(lb0, lb1);
                    *(uint32_t*)(ah + o1) = pk2(hb2, hb3);
                    *(uint32_t*)(al + o1) = pk2(lb2, lb3);
                } else {
                    size_t o = (size_t)bh_ * DKV * SS_ + (size_t)d * SS_;
                    vth[o + s_]       = hb0;  vtl[o + s_]       = lb0;
                    vth[o + SS_ + s_] = hb1;  vtl[o + SS_ + s_] = lb1;
                    vth[o + s2]       = hb2;  vtl[o + s2]       = lb2;
                    vth[o + SS_ + s2] = hb3;  vtl[o + SS_ + s2] = lb3;
                }
            }
        }
    } else {
#pragma unroll
        for (int mi = 0; mi < 4; mi++) {
            int m = m0 + wm * 64 + mi * 16 + g;
#pragma unroll
            for (int ni = 0; ni < 4; ni++) {
                int ncol = n0 + wn * 32 + ni * 8 + tc;
                float2 o0 = {scf * (accf[mi][ni][0] + (float)acc[mi][ni][0] * (1.f/256.f)) + b0p[ncol],
                             scf * (accf[mi][ni][1] + (float)acc[mi][ni][1] * (1.f/256.f)) + b0p[ncol + 1]};
                float2 o1 = {scf * (accf[mi][ni][2] + (float)acc[mi][ni][2] * (1.f/256.f)) + b0p[ncol],
                             scf * (accf[mi][ni][3] + (float)acc[mi][ni][3] * (1.f/256.f)) + b0p[ncol + 1]};
                *(float2*)(outp + (size_t)m * DM + ncol) = o0;
                *(float2*)(outp + (size_t)(m + 8) * DM + ncol) = o1;
            }
        }
    }
}

// ===========================================================================
// Scores GEMM (3-term bf16) — unchanged from R4
// ===========================================================================
__global__ __launch_bounds__(256) void k_scores(const float* __restrict__ bias, int mode)
{
    __shared__ __align__(16) char smem[2 * 2 * TILEB];
    const int tid = threadIdx.x, wid = tid >> 5, lane = tid & 31;
    const int wm = wid >> 2, wn = wid & 3;
    const int j0 = blockIdx.x * 128;

    const __nv_bfloat16 *A0, *A1, *B0, *B1;
    size_t rsA;
    int i0 = 0, bh = 0, iE = 0;
    if (mode == 0) {
        i0 = blockIdx.y * 128; bh = blockIdx.z;
        A0 = qh + ((size_t)bh * SS_ + i0) * DKV;
        A1 = ql + ((size_t)bh * SS_ + i0) * DKV;
        B0 = kh + ((size_t)bh * SS_ + j0) * DKV;
        B1 = kl + ((size_t)bh * SS_ + j0) * DKV;
        rsA = DKV;
    } else {
        iE = blockIdx.y;
        A0 = qh + (size_t)iE * DKV;
        A1 = ql + (size_t)iE * DKV;
        B0 = ekh + ((size_t)iE * SS_ + j0) * DKV;
        B1 = ekl + ((size_t)iE * SS_ + j0) * DKV;
        rsA = (size_t)SS_ * DKV;
    }
    const __nv_bfloat16* At[3] = {A0, A0, A1};
    const __nv_bfloat16* Bt[3] = {B0, B1, B0};

    const uint32_t sbase = s2u(smem);
    const int lrow0 = tid >> 2, lseg = (tid & 3) << 3;

    float acc[4][4][4];
#pragma unroll
    for (int i = 0; i < 4; i++)
#pragma unroll
        for (int j = 0; j < 4; j++)
#pragma unroll
            for (int q = 0; q < 4; q++) acc[i][j][q] = 0.f;

    {
        uint32_t dA = sbase, dB = sbase + TILEB;
#pragma unroll
        for (int u = 0; u < 2; u++) {
            int row = lrow0 + u * 64;
            CP_ASYNC16(dA + (row * LDS_ + lseg) * 2, At[0] + (size_t)row * rsA + lseg);
            CP_ASYNC16(dB + (row * LDS_ + lseg) * 2, Bt[0] + (size_t)row * DKV + lseg);
        }
        CP_COMMIT();
    }

    for (int c = 0; c < 6; c++) {
        CP_WAIT0();
        __syncthreads();

        if (c + 1 < 6) {
            int t2 = (c + 1) >> 1, ko2 = ((c + 1) & 1) * 32;
            uint32_t dA = sbase + ((c + 1) & 1) * 2 * TILEB;
            uint32_t dB = dA + TILEB;
#pragma unroll
            for (int u = 0; u < 2; u++) {
                int row = lrow0 + u * 64;
                CP_ASYNC16(dA + (row * LDS_ + lseg) * 2, At[t2] + (size_t)row * rsA + ko2 + lseg);
                CP_ASYNC16(dB + (row * LDS_ + lseg) * 2, Bt[t2] + (size_t)row * DKV + ko2 + lseg);
            }
            CP_COMMIT();
        }

        const uint32_t bufA = sbase + (c & 1) * 2 * TILEB;
        const uint32_t bufB = bufA + TILEB;
        const int lr = lane & 15, lc = (lane >> 4) << 3;

#pragma unroll
        for (int ks = 0; ks < 2; ks++) {
            uint32_t a[4][4];
#pragma unroll
            for (int mi = 0; mi < 4; mi++) {
                uint32_t addr = bufA + ((wm * 64 + mi * 16 + lr) * LDS_ + ks * 16 + lc) * 2;
                LDMATX4(a[mi][0], a[mi][1], a[mi][2], a[mi][3], addr);
            }
            uint32_t b[4][2];
#pragma unroll
            for (int ni2 = 0; ni2 < 2; ni2++) {
                uint32_t r0, r1, r2, r3;
                uint32_t addr = bufB + ((wn * 32 + ni2 * 16 + lr) * LDS_ + ks * 16 + lc) * 2;
                LDMATX4(r0, r1, r2, r3, addr);
                b[2 * ni2][0] = r0;     b[2 * ni2][1] = r2;
                b[2 * ni2 + 1][0] = r1; b[2 * ni2 + 1][1] = r3;
            }
#pragma unroll
            for (int mi = 0; mi < 4; mi++)
#pragma unroll
                for (int ni = 0; ni < 4; ni++)
                    MMA16816(acc[mi][ni], a[mi], b[ni]);
        }
        __syncthreads();
    }

    const int g = lane >> 2, tc = (lane & 3) << 1;
#pragma unroll
    for (int mi = 0; mi < 4; mi++) {
        int m = wm * 64 + mi * 16 + g;
#pragma unroll
        for (int ni = 0; ni < 4; ni++) {
            int jc = j0 + wn * 32 + ni * 8 + tc;
            if (mode == 0) {
                size_t base0 = ((size_t)bh * SS_ + (i0 + m)) * SS_ + jc;
                size_t base1 = base0 + 8 * SS_;
                float2 o0 = {acc[mi][ni][0] * SCALE + bias[base0],
                             acc[mi][ni][1] * SCALE + bias[base0 + 1]};
                float2 o1 = {acc[mi][ni][2] * SCALE + bias[base1],
                             acc[mi][ni][3] * SCALE + bias[base1 + 1]};
                *(float2*)(g_sc + base0) = o0;
                *(float2*)(g_sc + base1) = o1;
            } else {
                size_t base0 = ((size_t)m * SS_ + iE) * SS_ + jc;
                size_t base1 = base0 + (size_t)8 * SS_ * SS_;
                float2 p0 = *(float2*)(g_sc + base0);
                float2 p1 = *(float2*)(g_sc + base1);
                p0.x += acc[mi][ni][0] * SCALE; p0.y += acc[mi][ni][1] * SCALE;
                p1.x += acc[mi][ni][2] * SCALE; p1.y += acc[mi][ni][3] * SCALE;
                *(float2*)(g_sc + base0) = p0;
                *(float2*)(g_sc + base1) = p1;
            }
        }
    }
}

// ===========================================================================
// Softmax + split (unchanged)
// ===========================================================================
__global__ __launch_bounds__(256) void k_softmax_split()
{
    const int warp = threadIdx.x >> 5, lane = threadIdx.x & 31;
    const size_t row = (size_t)blockIdx.x * 8 + warp;
    const float* p = g_sc + row * SS_;

    float4 v[4];
    float mx = -1e30f;
#pragma unroll
    for (int w = 0; w < 4; w++) {
        v[w] = *(const float4*)(p + w * 128 + lane * 4);
        mx = fmaxf(mx, fmaxf(fmaxf(v[w].x, v[w].y), fmaxf(v[w].z, v[w].w)));
    }
#pragma unroll
    for (int o = 16; o > 0; o >>= 1) mx = fmaxf(mx, __shfl_xor_sync(~0u, mx, o));

    float sum = 0.f;
#pragma unroll
    for (int w = 0; w < 4; w++) {
        v[w].x = __expf(v[w].x - mx); v[w].y = __expf(v[w].y - mx);
        v[w].z = __expf(v[w].z - mx); v[w].w = __expf(v[w].w - mx);
        sum += v[w].x + v[w].y + v[w].z + v[w].w;
    }
#pragma unroll
    for (int o = 16; o > 0; o >>= 1) sum += __shfl_xor_sync(~0u, sum, o);
    float r = 1.f / sum;
#pragma unroll
    for (int w = 0; w < 4; w++) {
        float f[4] = {v[w].x * r, v[w].y * r, v[w].z * r, v[w].w * r};
        uint32_t hu[2], lu[2];
#pragma unroll
        for (int pq = 0; pq < 2; pq++) {
            __nv_bfloat16 h0 = __float2bfloat16(f[2*pq]);
            __nv_bfloat16 h1 = __float2bfloat16(f[2*pq+1]);
            __nv_bfloat16 l0 = __float2bfloat16(f[2*pq]   - __bfloat162float(h0));
            __nv_bfloat16 l1 = __float2bfloat16(f[2*pq+1] - __bfloat162float(h1));
            hu[pq] = pk2(h0, h1); lu[pq] = pk2(l0, l1);
        }
        size_t off = row * SS_ + w * 128 + lane * 4;
        *(uint2*)(wh + off) = make_uint2(hu[0], hu[1]);
        *(uint2*)(wl + off) = make_uint2(lu[0], lu[1]);
    }
}

// ===========================================================================
// Context GEMM (3-term bf16) — unchanged from R4
// ===========================================================================
#define CT_A_TILEB (128 * LDS_ * 2)
#define CT_B_TILEB (64 * LDS_ * 2)
#define CT_STAGE   (CT_A_TILEB + CT_B_TILEB)

__global__ __launch_bounds__(256) void k_ctx(int mode)
{
    __shared__ __align__(16) char smem[2 * CT_STAGE];
    const int tid = threadIdx.x, wid = tid >> 5, lane = tid & 31;
    const int wm = wid >> 1, wn = wid & 1;

    const __nv_bfloat16 *A0, *A1, *B0, *B1;
    size_t rsA;
    int i0 = 0, bh = 0, iE = 0;
    if (mode == 0) {
        bh = blockIdx.y; i0 = blockIdx.x * 128;
        A0 = wh + (size_t)bh * SS_ * SS_ + (size_t)i0 * SS_;
        A1 = wl + (size_t)bh * SS_ * SS_ + (size_t)i0 * SS_;
        B0 = vth + (size_t)bh * DKV * SS_;
        B1 = vtl + (size_t)bh * DKV * SS_;
        rsA = SS_;
    } else {
        iE = blockIdx.x;
        A0 = wh + (size_t)iE * SS_;
        A1 = wl + (size_t)iE * SS_;
        B0 = evth + (size_t)iE * DKV * SS_;
        B1 = evtl + (size_t)iE * DKV * SS_;
        rsA = (size_t)SS_ * SS_;
    }
    const __nv_bfloat16* At[3] = {A0, A0, A1};
    const __nv_bfloat16* Bt[3] = {B0, B1, B0};

    const uint32_t sbase = s2u(smem);
    const int arow = tid >> 1, aseg = (tid & 1) << 4;
    const int brow = tid >> 2, bseg = (tid & 3) << 3;

    float acc[2][4][4];
#pragma unroll
    for (int i = 0; i < 2; i++)
#pragma unroll
        for (int j = 0; j < 4; j++)
#pragma unroll
            for (int q = 0; q < 4; q++) acc[i][j][q] = 0.f;

    {
        uint32_t dA = sbase, dB = sbase + CT_A_TILEB;
        CP_ASYNC16(dA + (arow * LDS_ + aseg) * 2,     At[0] + (size_t)arow * rsA + aseg);
        CP_ASYNC16(dA + (arow * LDS_ + aseg + 8) * 2, At[0] + (size_t)arow * rsA + aseg + 8);
        CP_ASYNC16(dB + (brow * LDS_ + bseg) * 2,     Bt[0] + (size_t)brow * SS_ + bseg);
        CP_COMMIT();
    }

    for (int c = 0; c < 48; c++) {
        CP_WAIT0();
        __syncthreads();

        if (c + 1 < 48) {
            int t2 = (c + 1) >> 4, ko2 = ((c + 1) & 15) * 32;
            uint32_t dA = sbase + ((c + 1) & 1) * CT_STAGE;
            uint32_t dB = dA + CT_A_TILEB;
            CP_ASYNC16(dA + (arow * LDS_ + aseg) * 2,     At[t2] + (size_t)arow * rsA + ko2 + aseg);
            CP_ASYNC16(dA + (arow * LDS_ + aseg + 8) * 2, At[t2] + (size_t)arow * rsA + ko2 + aseg + 8);
            CP_ASYNC16(dB + (brow * LDS_ + bseg) * 2,     Bt[t2] + (size_t)brow * SS_ + ko2 + bseg);
            CP_COMMIT();
        }

        const uint32_t bufA = sbase + (c & 1) * CT_STAGE;
        const uint32_t bufB = bufA + CT_A_TILEB;
        const int lr = lane & 15, lc = (lane >> 4) << 3;

#pragma unroll
        for (int ks = 0; ks < 2; ks++) {
            uint32_t a[2][4];
#pragma unroll
            for (int mi = 0; mi < 2; mi++) {
                uint32_t addr = bufA + ((wm * 32 + mi * 16 + lr) * LDS_ + ks * 16 + lc) * 2;
                LDMATX4(a[mi][0], a[mi][1], a[mi][2], a[mi][3], addr);
            }
            uint32_t b[4][2];
#pragma unroll
            for (int ni2 = 0; ni2 < 2; ni2++) {
                uint32_t r0, r1, r2, r3;
                uint32_t addr = bufB + ((wn * 32 + ni2 * 16 + lr) * LDS_ + ks * 16 + lc) * 2;
                LDMATX4(r0, r1, r2, r3, addr);
                b[2 * ni2][0] = r0;     b[2 * ni2][1] = r2;
                b[2 * ni2 + 1][0] = r1; b[2 * ni2 + 1][1] = r3;
            }
#pragma unroll
            for (int mi = 0; mi < 2; mi++)
#pragma unroll
                for (int ni = 0; ni < 4; ni++)
                    MMA16816(acc[mi][ni], a[mi], b[ni]);
        }
        __syncthreads();
    }

    const int g = lane >> 2, tc = (lane & 3) << 1;
#pragma unroll
    for (int mi = 0; mi < 2; mi++) {
        int m = wm * 32 + mi * 16 + g;
#pragma unroll
        for (int ni = 0; ni < 4; ni++) {
            int ncol = wn * 32 + ni * 8 + tc;
            if (mode == 0) {
                int i = i0 + m;
                size_t a0 = ((size_t)(bh >> 4) * SS_ + i) * DM + (bh & 15) * DKV + ncol;
                size_t a1 = a0 + (size_t)8 * DM;
                float2 o0 = {acc[mi][ni][0], acc[mi][ni][1]};
                float2 o1 = {acc[mi][ni][2], acc[mi][ni][3]};
                *(float2*)(g_ctx + a0) = o0;
                *(float2*)(g_ctx + a1) = o1;
            } else {
                int bh0 = m, bh1 = m + 8;
                size_t a0 = ((size_t)(bh0 >> 4) * SS_ + iE) * DM + (bh0 & 15) * DKV + ncol;
                size_t a1 = ((size_t)(bh1 >> 4) * SS_ + iE) * DM + (bh1 & 15) * DKV + ncol;
                float2 p0 = *(float2*)(g_ctx + a0);
                float2 p1 = *(float2*)(g_ctx + a1);
                p0.x += acc[mi][ni][0]; p0.y += acc[mi][ni][1];
                p1.x += acc[mi][ni][2]; p1.y += acc[mi][ni][3];
                *(float2*)(g_ctx + a0) = p0;
                *(float2*)(g_ctx + a1) = p1;
            }
        }
    }
}

// ===========================================================================
// Launcher
// ===========================================================================
extern "C" void kernel_launch(void* const* d_in, const int* in_sizes, int n_in,
                              void* d_out, int out_size)
{
    const float* queries     = (const float*)d_in[0];
    const float* edges_key   = (const float*)d_in[1];
    const float* edges_value = (const float*)d_in[2];
    const float* attn_bias   = (const float*)d_in[3];
    const float* Wq = (const float*)d_in[4];
    const float* bq = (const float*)d_in[5];
    const float* Wk = (const float*)d_in[6];
    const float* bk = (const float*)d_in[7];
    const float* Wv = (const float*)d_in[8];
    const float* bv = (const float*)d_in[9];
    const float* Wo = (const float*)d_in[10];
    const float* bo = (const float*)d_in[11];
    float* out = (float*)d_out;

    cudaStream_t st = 0;
    cudaStreamCaptureStatus cs = cudaStreamCaptureStatusNone;
    if (cudaStreamIsCapturing(cudaStreamPerThread, &cs) == cudaSuccess &&
        cs == cudaStreamCaptureStatusActive)
        st = cudaStreamPerThread;

    // scales (re-zeroed each replay for graph determinism)
    k_amax_init<<<1, 32, 0, st>>>();
    k_amax<<<256, 256, 0, st>>>(queries, 4096 * 1024, 0);
    k_amax<<<64, 256, 0, st>>>(Wq, 1024 * 1024, 1);
    k_amax<<<64, 256, 0, st>>>(Wk, 1024 * 1024, 2);
    k_amax<<<64, 256, 0, st>>>(Wv, 1024 * 1024, 3);
    k_amax<<<64, 256, 0, st>>>(Wo, 1024 * 1024, 4);

    // quantize projection operands
    k_quant_x<<<2048, 256, 0, st>>>(queries, 0);
    k_quant_w<<<dim3(4, 128, 4), 256, 0, st>>>(Wq, Wk, Wv, Wo);

    // edge splits (bf16)
    k_split_ek <<<8192, 256, 0, st>>>(edges_key);
    k_split_evt<<<dim3(16, 2, 512), 256, 0, st>>>(edges_value);

    // QKV projection on int8 IMMA -> q/k splits + transposed-v splits
    k_gemm_s8<<<dim3(24, 32), 256, 0, st>>>(bq, bk, bv, nullptr, 0);

    // scores: content (write + bias), then edge (accumulate)
    k_scores<<<dim3(4, 4, 128), 256, 0, st>>>(attn_bias, 0);
    k_scores<<<dim3(4, 512),    256, 0, st>>>(nullptr, 1);

    // softmax -> bf16 split weights
    k_softmax_split<<<8192, 256, 0, st>>>();

    // context: content (write), then edge (accumulate)
    k_ctx<<<dim3(4, 128), 256, 0, st>>>(0);
    k_ctx<<<dim3(512),    256, 0, st>>>(1);

    // output projection on int8 IMMA
    k_amax<<<256, 256, 0, st>>>(nullptr, BB * SS_ * DM, 5);
    k_quant_x<<<2048, 256, 0, st>>>(nullptr, 1);
    k_gemm_s8<<<dim3(8, 32), 256, 0, st>>>(bo, nullptr, nullptr, out, 1);
}

// round 6
// speedup vs baseline: 1.5757x; 1.5757x over previous
#include <cuda_runtime.h>
#include <cuda_bf16.h>
#include <cstdint>

// ---------------------------------------------------------------------------
// Problem constants: B=8, S=512, D_MODEL=1024, H=16, DK=DV=64, BH=128
// ---------------------------------------------------------------------------
#define BB   8
#define SS_  512
#define DM   1024
#define HH   16
#define DKV  64
#define BH   128
#define SCALE 0.125f

// ---------------------------------------------------------------------------
// Scratch (device globals)
// ---------------------------------------------------------------------------
__device__ float g_sc [(size_t)BH * SS_ * SS_];    // scores fp32 [bh,i,j]
__device__ float g_ctx[(size_t)BB * SS_ * DM];     // context fp32

// projection staging (3-term replicated layout)
__device__ __align__(16) __nv_bfloat16 g_A   [(size_t)4096 * 3072];
__device__ __align__(16) __nv_bfloat16 g_Actx[(size_t)4096 * 3072];
__device__ __align__(16) __nv_bfloat16 g_Bqkv[(size_t)3072 * 3072];
__device__ __align__(16) __nv_bfloat16 g_Bo  [(size_t)1024 * 3072];

// attention operand splits (hi/lo bf16)
__device__ __align__(16) __nv_bfloat16 qh [(size_t)BH * SS_ * DKV];
__device__ __align__(16) __nv_bfloat16 ql [(size_t)BH * SS_ * DKV];
__device__ __align__(16) __nv_bfloat16 kh [(size_t)BH * SS_ * DKV];
__device__ __align__(16) __nv_bfloat16 kl [(size_t)BH * SS_ * DKV];
__device__ __align__(16) __nv_bfloat16 vth[(size_t)BH * DKV * SS_];  // [bh,d,s]
__device__ __align__(16) __nv_bfloat16 vtl[(size_t)BH * DKV * SS_];
__device__ __align__(16) __nv_bfloat16 ekh [(size_t)SS_ * SS_ * DKV]; // [i,j,d]
__device__ __align__(16) __nv_bfloat16 ekl [(size_t)SS_ * SS_ * DKV];
__device__ __align__(16) __nv_bfloat16 evth[(size_t)SS_ * DKV * SS_]; // [i,d,j]
__device__ __align__(16) __nv_bfloat16 evtl[(size_t)SS_ * DKV * SS_];
__device__ __align__(16) __nv_bfloat16 wh [(size_t)BH * SS_ * SS_];   // [bh,i,j]
__device__ __align__(16) __nv_bfloat16 wl [(size_t)BH * SS_ * SS_];

__device__ __forceinline__ uint32_t s2u(const void* p) {
    uint32_t a;
    asm("{ .reg .u64 t; cvta.to.shared.u64 t, %1; cvt.u32.u64 %0, t; }"
        : "=r"(a) : "l"(p));
    return a;
}
__device__ __forceinline__ uint32_t pk2(__nv_bfloat16 a, __nv_bfloat16 b) {
    return (uint32_t)__bfloat16_as_ushort(a) | ((uint32_t)__bfloat16_as_ushort(b) << 16);
}

#define CP_ASYNC16(dst, src) \
    asm volatile("cp.async.cg.shared.global [%0], [%1], 16;" :: "r"(dst), "l"(src) : "memory")
#define CP_COMMIT() asm volatile("cp.async.commit_group;" ::: "memory")
#define CP_WAIT0()  asm volatile("cp.async.wait_group 0;" ::: "memory")
#define CP_WAIT1()  asm volatile("cp.async.wait_group 1;" ::: "memory")

#define LDMATX4(r0, r1, r2, r3, addr) \
    asm volatile("ldmatrix.sync.aligned.m8n8.x4.shared.b16 {%0,%1,%2,%3}, [%4];" \
        : "=r"(r0), "=r"(r1), "=r"(r2), "=r"(r3) : "r"(addr))

#define MMA16816(c, a, b) \
    asm volatile("mma.sync.aligned.m16n8k16.row.col.f32.bf16.bf16.f32 " \
        "{%0,%1,%2,%3}, {%4,%5,%6,%7}, {%8,%9}, {%0,%1,%2,%3};" \
        : "+f"((c)[0]), "+f"((c)[1]), "+f"((c)[2]), "+f"((c)[3]) \
        : "r"((a)[0]), "r"((a)[1]), "r"((a)[2]), "r"((a)[3]), \
          "r"((b)[0]), "r"((b)[1]))

#define LDS_   40                 // padded row stride in bf16 (80 bytes)
#define TILEB  (128 * LDS_ * 2)   // 10240 bytes
#define GSMEM  (3 * 2 * TILEB)    // 61440: 3-stage double-matrix buffers

// ===========================================================================
// Split conversion: fp32 [4096,1024] -> bf16 split [4096,3072]
// which=0: src=queries -> g_A ; which=1: src=g_ctx -> g_Actx
// ===========================================================================
__global__ __launch_bounds__(256) void k_split(const float* __restrict__ src_in, int which)
{
    const float* src = which ? (const float*)g_ctx : src_in;
    __nv_bfloat16* dst = which ? g_Actx : g_A;
    int idx = blockIdx.x * 256 + threadIdx.x;
    int r = idx >> 7;
    int c0 = (idx & 127) << 3;
    const float* s = src + (size_t)r * 1024 + c0;
    float4 v0 = *(const float4*)(s);
    float4 v1 = *(const float4*)(s + 4);
    float f[8] = {v0.x, v0.y, v0.z, v0.w, v1.x, v1.y, v1.z, v1.w};
    uint4 H, L;
    uint32_t hu[4], lu[4];
#pragma unroll
    for (int i = 0; i < 4; i++) {
        __nv_bfloat16 h0 = __float2bfloat16(f[2*i]);
        __nv_bfloat16 h1 = __float2bfloat16(f[2*i+1]);
        __nv_bfloat16 l0 = __float2bfloat16(f[2*i]   - __bfloat162float(h0));
        __nv_bfloat16 l1 = __float2bfloat16(f[2*i+1] - __bfloat162float(h1));
        hu[i] = pk2(h0, h1); lu[i] = pk2(l0, l1);
    }
    H.x = hu[0]; H.y = hu[1]; H.z = hu[2]; H.w = hu[3];
    L.x = lu[0]; L.y = lu[1]; L.z = lu[2]; L.w = lu[3];
    __nv_bfloat16* row = dst + (size_t)r * 3072;
    *(uint4*)(row + c0)        = H;
    *(uint4*)(row + 1024 + c0) = H;
    *(uint4*)(row + 2048 + c0) = L;
}

// ===========================================================================
// Weight split+transpose (4 weights, one launch): W[1024k,1024n]->B'[n][3072]
// ===========================================================================
__global__ __launch_bounds__(256) void k_wsplit(
    const float* __restrict__ W0, const float* __restrict__ W1,
    const float* __restrict__ W2, const float* __restrict__ W3)
{
    const int slot = blockIdx.z;
    const float* W = (slot == 0) ? W0 : (slot == 1) ? W1 : (slot == 2) ? W2 : W3;
    __nv_bfloat16* dst = (slot < 3) ? (g_Bqkv + (size_t)slot * 1024 * 3072) : g_Bo;
    int nl = blockIdx.x * 256 + threadIdx.x;
    int k0 = blockIdx.y << 3;
    uint4 H, L;
    uint32_t hu[4], lu[4];
#pragma unroll
    for (int i = 0; i < 4; i++) {
        float f0 = W[(size_t)(k0 + 2*i)     * 1024 + nl];
        float f1 = W[(size_t)(k0 + 2*i + 1) * 1024 + nl];
        __nv_bfloat16 h0 = __float2bfloat16(f0);
        __nv_bfloat16 h1 = __float2bfloat16(f1);
        __nv_bfloat16 l0 = __float2bfloat16(f0 - __bfloat162float(h0));
        __nv_bfloat16 l1 = __float2bfloat16(f1 - __bfloat162float(h1));
        hu[i] = pk2(h0, h1); lu[i] = pk2(l0, l1);
    }
    H.x = hu[0]; H.y = hu[1]; H.z = hu[2]; H.w = hu[3];
    L.x = lu[0]; L.y = lu[1]; L.z = lu[2]; L.w = lu[3];
    __nv_bfloat16* row = dst + (size_t)nl * 3072;
    *(uint4*)(row + k0)        = H;
    *(uint4*)(row + 1024 + k0) = L;
    *(uint4*)(row + 2048 + k0) = H;
}

// ===========================================================================
// EK split: fp32 [i,j,64] -> ekh/ekl bf16 (elementwise)
// ===========================================================================
__global__ __launch_bounds__(256) void k_split_ek(const float* __restrict__ EK)
{
    size_t base = ((size_t)blockIdx.x * 256 + threadIdx.x) * 8;
    float4 v0 = *(const float4*)(EK + base);
    float4 v1 = *(const float4*)(EK + base + 4);
    float f[8] = {v0.x, v0.y, v0.z, v0.w, v1.x, v1.y, v1.z, v1.w};
    uint4 H, L;
    uint32_t hu[4], lu[4];
#pragma unroll
    for (int i = 0; i < 4; i++) {
        __nv_bfloat16 h0 = __float2bfloat16(f[2*i]);
        __nv_bfloat16 h1 = __float2bfloat16(f[2*i+1]);
        __nv_bfloat16 l0 = __float2bfloat16(f[2*i]   - __bfloat162float(h0));
        __nv_bfloat16 l1 = __float2bfloat16(f[2*i+1] - __bfloat162float(h1));
        hu[i] = pk2(h0, h1); lu[i] = pk2(l0, l1);
    }
    H.x = hu[0]; H.y = hu[1]; H.z = hu[2]; H.w = hu[3];
    L.x = lu[0]; L.y = lu[1]; L.z = lu[2]; L.w = lu[3];
    *(uint4*)(ekh + base) = H;
    *(uint4*)(ekl + base) = L;
}

// ===========================================================================
// EV transpose-split: fp32 [i,j,64] -> evth/evtl bf16 [i,64,512]
// ===========================================================================
__global__ __launch_bounds__(256) void k_split_evt(const float* __restrict__ EV)
{
    __shared__ float ts[32][33];
    const int jt = blockIdx.x, dt = blockIdx.y, i = blockIdx.z;
    const int t = threadIdx.x;
    const int r = t >> 3, c0 = (t & 7) << 2;

    float4 v = *(const float4*)(EV + ((size_t)(i * SS_ + jt * 32 + r)) * DKV + dt * 32 + c0);
    ts[r][c0 + 0] = v.x; ts[r][c0 + 1] = v.y;
    ts[r][c0 + 2] = v.z; ts[r][c0 + 3] = v.w;
    __syncthreads();

    uint32_t hu[2], lu[2];
#pragma unroll
    for (int p = 0; p < 2; p++) {
        float f0 = ts[c0 + 2*p][r];
        float f1 = ts[c0 + 2*p + 1][r];
        __nv_bfloat16 h0 = __float2bfloat16(f0);
        __nv_bfloat16 h1 = __float2bfloat16(f1);
        __nv_bfloat16 l0 = __float2bfloat16(f0 - __bfloat162float(h0));
        __nv_bfloat16 l1 = __float2bfloat16(f1 - __bfloat162float(h1));
        hu[p] = pk2(h0, h1); lu[p] = pk2(l0, l1);
    }
    size_t off = ((size_t)i * DKV + dt * 32 + r) * SS_ + jt * 32 + c0;
    *(uint2*)(evth + off) = make_uint2(hu[0], hu[1]);
    *(uint2*)(evtl + off) = make_uint2(lu[0], lu[1]);
}

// ===========================================================================
// bf16 mma.sync GEMM (projections): C[4096,N] = A'[4096,3072] @ B'[N,3072]^T
// 128x128 CTA, 8 warps 64x32, BK=32, 3-stage cp.async pipeline.
// mode 0: QKV -> q/k splits + transposed-v splits; mode 1: OUT -> outp
// ===========================================================================
#define KTOT   3072
#define NCHUNK 96

__global__ __launch_bounds__(256) void k_gemm_bf16(
    const float* __restrict__ b0p, const float* __restrict__ b1p,
    const float* __restrict__ b2p, float* __restrict__ outp, int mode)
{
    extern __shared__ __align__(16) char smem[];   // 3 * 2 * TILEB

    const int tid  = threadIdx.x;
    const int wid  = tid >> 5, lane = tid & 31;
    const int wm   = wid >> 2, wn = wid & 3;
    const int m0   = blockIdx.y * 128, n0 = blockIdx.x * 128;
    const uint32_t sbase = s2u(smem);

    const __nv_bfloat16* __restrict__ Ag = mode ? g_Actx : g_A;
    const __nv_bfloat16* __restrict__ Bg = mode ? g_Bo   : g_Bqkv;

    const int lrow0 = tid >> 2;
    const int lseg  = (tid & 3) << 3;

    float acc[4][4][4];
#pragma unroll
    for (int i = 0; i < 4; i++)
#pragma unroll
        for (int j = 0; j < 4; j++)
#pragma unroll
            for (int q = 0; q < 4; q++) acc[i][j][q] = 0.f;

    // prologue: chunks 0,1 -> stages 0,1
#pragma unroll
    for (int pc = 0; pc < 2; pc++) {
        uint32_t dA = sbase + pc * (2 * TILEB), dB = dA + TILEB;
        const int koff = pc * 32 + lseg;
#pragma unroll
        for (int u = 0; u < 2; u++) {
            int row = lrow0 + u * 64;
            CP_ASYNC16(dA + (row * LDS_ + lseg) * 2, Ag + (size_t)(m0 + row) * KTOT + koff);
            CP_ASYNC16(dB + (row * LDS_ + lseg) * 2, Bg + (size_t)(n0 + row) * KTOT + koff);
        }
        CP_COMMIT();
    }

    for (int c = 0; c < NCHUNK; c++) {
        if (c + 1 < NCHUNK) CP_WAIT1(); else CP_WAIT0();
        __syncthreads();

        if (c + 2 < NCHUNK) {
            uint32_t dA = sbase + ((c + 2) % 3) * (2 * TILEB);
            uint32_t dB = dA + TILEB;
            const int koff = (c + 2) * 32 + lseg;
#pragma unroll
            for (int u = 0; u < 2; u++) {
                int row = lrow0 + u * 64;
                CP_ASYNC16(dA + (row * LDS_ + lseg) * 2, Ag + (size_t)(m0 + row) * KTOT + koff);
                CP_ASYNC16(dB + (row * LDS_ + lseg) * 2, Bg + (size_t)(n0 + row) * KTOT + koff);
            }
            CP_COMMIT();
        }

        const uint32_t bufA = sbase + (c % 3) * (2 * TILEB);
        const uint32_t bufB = bufA + TILEB;
        const int lr = lane & 15, lc = (lane >> 4) << 3;

#pragma unroll
        for (int ks = 0; ks < 2; ks++) {
            uint32_t a[4][4];
#pragma unroll
            for (int mi = 0; mi < 4; mi++) {
                uint32_t addr = bufA + ((wm * 64 + mi * 16 + lr) * LDS_ + ks * 16 + lc) * 2;
                LDMATX4(a[mi][0], a[mi][1], a[mi][2], a[mi][3], addr);
            }
            uint32_t b[4][2];
#pragma unroll
            for (int ni2 = 0; ni2 < 2; ni2++) {
                uint32_t r0, r1, r2, r3;
                uint32_t addr = bufB + ((wn * 32 + ni2 * 16 + lr) * LDS_ + ks * 16 + lc) * 2;
                LDMATX4(r0, r1, r2, r3, addr);
                b[2 * ni2][0] = r0;     b[2 * ni2][1] = r2;
                b[2 * ni2 + 1][0] = r1; b[2 * ni2 + 1][1] = r3;
            }
#pragma unroll
            for (int mi = 0; mi < 4; mi++)
#pragma unroll
                for (int ni = 0; ni < 4; ni++)
                    MMA16816(acc[mi][ni], a[mi], b[ni]);
        }
    }

    // -------- epilogue --------
    const int g  = lane >> 2;
    const int tc = (lane & 3) << 1;

    if (mode == 0) {
        const int proj = n0 >> 10;
        const float* bias = (proj == 0) ? b0p : (proj == 1) ? b1p : b2p;
#pragma unroll
        for (int mi = 0; mi < 4; mi++) {
            int m = m0 + wm * 64 + mi * 16 + g;
            int b_ = m >> 9, s_ = m & 511;
            int s2 = s_ + 8;
#pragma unroll
            for (int ni = 0; ni < 4; ni++) {
                int nl = (n0 & 1023) + wn * 32 + ni * 8 + tc;
                int hd = nl >> 6, d = nl & 63;
                int bh_ = b_ * HH + hd;
                float x0 = acc[mi][ni][0] + bias[nl];
                float x1 = acc[mi][ni][1] + bias[nl + 1];
                float x2 = acc[mi][ni][2] + bias[nl];
                float x3 = acc[mi][ni][3] + bias[nl + 1];
                __nv_bfloat16 hb0 = __float2bfloat16(x0), lb0 = __float2bfloat16(x0 - __bfloat162float(hb0));
                __nv_bfloat16 hb1 = __float2bfloat16(x1), lb1 = __float2bfloat16(x1 - __bfloat162float(hb1));
                __nv_bfloat16 hb2 = __float2bfloat16(x2), lb2 = __float2bfloat16(x2 - __bfloat162float(hb2));
                __nv_bfloat16 hb3 = __float2bfloat16(x3), lb3 = __float2bfloat16(x3 - __bfloat162float(hb3));
                if (proj < 2) {
                    __nv_bfloat16* ah = (proj == 0) ? qh : kh;
                    __nv_bfloat16* al = (proj == 0) ? ql : kl;
                    size_t o0 = ((size_t)bh_ * SS_ + s_) * DKV + d;
                    size_t o1 = o0 + 8 * DKV;
                    *(uint32_t*)(ah + o0) = pk2(hb0, hb1);
                    *(uint32_t*)(al + o0) = pk2(lb0, lb1);
                    *(uint32_t*)(ah + o1) = pk2(hb2, hb3);
                    *(uint32_t*)(al + o1) = pk2(lb2, lb3);
                } else {
                    size_t o = (size_t)bh_ * DKV * SS_ + (size_t)d * SS_;
                    vth[o + s_]       = hb0;  vtl[o + s_]       = lb0;
                    vth[o + SS_ + s_] = hb1;  vtl[o + SS_ + s_] = lb1;
                    vth[o + s2]       = hb2;  vtl[o + s2]       = lb2;
                    vth[o + SS_ + s2] = hb3;  vtl[o + SS_ + s2] = lb3;
                }
            }
        }
    } else {
#pragma unroll
        for (int mi = 0; mi < 4; mi++) {
            int m = m0 + wm * 64 + mi * 16 + g;
#pragma unroll
            for (int ni = 0; ni < 4; ni++) {
                int ncol = n0 + wn * 32 + ni * 8 + tc;
                float2 o0 = {acc[mi][ni][0] + b0p[ncol],
                             acc[mi][ni][1] + b0p[ncol + 1]};
                float2 o1 = {acc[mi][ni][2] + b0p[ncol],
                             acc[mi][ni][3] + b0p[ncol + 1]};
                *(float2*)(outp + (size_t)m * DM + ncol) = o0;
                *(float2*)(outp + (size_t)(m + 8) * DM + ncol) = o1;
            }
        }
    }
}

// ===========================================================================
// Scores GEMM (3-term bf16, 128x128 CTA, 6 chunks of 32, 3-stage pipeline)
// mode 0 (content): grid(4 jt, 4 it, 128 bh): g_sc = acc*SCALE + bias
// mode 1 (edge):    grid(4 jt, 512 i):        g_sc += acc*SCALE
// ===========================================================================
__global__ __launch_bounds__(256) void k_scores(const float* __restrict__ bias, int mode)
{
    extern __shared__ __align__(16) char smem[];   // 3 * 2 * TILEB
    const int tid = threadIdx.x, wid = tid >> 5, lane = tid & 31;
    const int wm = wid >> 2, wn = wid & 3;
    const int j0 = blockIdx.x * 128;

    const __nv_bfloat16 *A0, *A1, *B0, *B1;
    size_t rsA;
    int i0 = 0, bh = 0, iE = 0;
    if (mode == 0) {
        i0 = blockIdx.y * 128; bh = blockIdx.z;
        A0 = qh + ((size_t)bh * SS_ + i0) * DKV;
        A1 = ql + ((size_t)bh * SS_ + i0) * DKV;
        B0 = kh + ((size_t)bh * SS_ + j0) * DKV;
        B1 = kl + ((size_t)bh * SS_ + j0) * DKV;
        rsA = DKV;
    } else {
        iE = blockIdx.y;
        A0 = qh + (size_t)iE * DKV;
        A1 = ql + (size_t)iE * DKV;
        B0 = ekh + ((size_t)iE * SS_ + j0) * DKV;
        B1 = ekl + ((size_t)iE * SS_ + j0) * DKV;
        rsA = (size_t)SS_ * DKV;
    }
    const __nv_bfloat16* At[3] = {A0, A0, A1};
    const __nv_bfloat16* Bt[3] = {B0, B1, B0};

    const uint32_t sbase = s2u(smem);
    const int lrow0 = tid >> 2, lseg = (tid & 3) << 3;

    float acc[4][4][4];
#pragma unroll
    for (int i = 0; i < 4; i++)
#pragma unroll
        for (int j = 0; j < 4; j++)
#pragma unroll
            for (int q = 0; q < 4; q++) acc[i][j][q] = 0.f;

#pragma unroll
    for (int pc = 0; pc < 2; pc++) {
        uint32_t dA = sbase + pc * (2 * TILEB), dB = dA + TILEB;
        int t2 = pc >> 1, ko2 = (pc & 1) * 32 + lseg;
#pragma unroll
        for (int u = 0; u < 2; u++) {
            int row = lrow0 + u * 64;
            CP_ASYNC16(dA + (row * LDS_ + lseg) * 2, At[t2] + (size_t)row * rsA + ko2);
            CP_ASYNC16(dB + (row * LDS_ + lseg) * 2, Bt[t2] + (size_t)row * DKV + ko2);
        }
        CP_COMMIT();
    }

    for (int c = 0; c < 6; c++) {
        if (c + 1 < 6) CP_WAIT1(); else CP_WAIT0();
        __syncthreads();

        if (c + 2 < 6) {
            int t2 = (c + 2) >> 1, ko2 = ((c + 2) & 1) * 32 + lseg;
            uint32_t dA = sbase + ((c + 2) % 3) * (2 * TILEB);
            uint32_t dB = dA + TILEB;
#pragma unroll
            for (int u = 0; u < 2; u++) {
                int row = lrow0 + u * 64;
                CP_ASYNC16(dA + (row * LDS_ + lseg) * 2, At[t2] + (size_t)row * rsA + ko2);
                CP_ASYNC16(dB + (row * LDS_ + lseg) * 2, Bt[t2] + (size_t)row * DKV + ko2);
            }
            CP_COMMIT();
        }

        const uint32_t bufA = sbase + (c % 3) * (2 * TILEB);
        const uint32_t bufB = bufA + TILEB;
        const int lr = lane & 15, lc = (lane >> 4) << 3;

#pragma unroll
        for (int ks = 0; ks < 2; ks++) {
            uint32_t a[4][4];
#pragma unroll
            for (int mi = 0; mi < 4; mi++) {
                uint32_t addr = bufA + ((wm * 64 + mi * 16 + lr) * LDS_ + ks * 16 + lc) * 2;
                LDMATX4(a[mi][0], a[mi][1], a[mi][2], a[mi][3], addr);
            }
            uint32_t b[4][2];
#pragma unroll
            for (int ni2 = 0; ni2 < 2; ni2++) {
                uint32_t r0, r1, r2, r3;
                uint32_t addr = bufB + ((wn * 32 + ni2 * 16 + lr) * LDS_ + ks * 16 + lc) * 2;
                LDMATX4(r0, r1, r2, r3, addr);
                b[2 * ni2][0] = r0;     b[2 * ni2][1] = r2;
                b[2 * ni2 + 1][0] = r1; b[2 * ni2 + 1][1] = r3;
            }
#pragma unroll
            for (int mi = 0; mi < 4; mi++)
#pragma unroll
                for (int ni = 0; ni < 4; ni++)
                    MMA16816(acc[mi][ni], a[mi], b[ni]);
        }
    }

    const int g = lane >> 2, tc = (lane & 3) << 1;
#pragma unroll
    for (int mi = 0; mi < 4; mi++) {
        int m = wm * 64 + mi * 16 + g;
#pragma unroll
        for (int ni = 0; ni < 4; ni++) {
            int jc = j0 + wn * 32 + ni * 8 + tc;
            if (mode == 0) {
                size_t base0 = ((size_t)bh * SS_ + (i0 + m)) * SS_ + jc;
                size_t base1 = base0 + 8 * SS_;
                float2 o0 = {acc[mi][ni][0] * SCALE + bias[base0],
                             acc[mi][ni][1] * SCALE + bias[base0 + 1]};
                float2 o1 = {acc[mi][ni][2] * SCALE + bias[base1],
                             acc[mi][ni][3] * SCALE + bias[base1 + 1]};
                *(float2*)(g_sc + base0) = o0;
                *(float2*)(g_sc + base1) = o1;
            } else {
                size_t base0 = ((size_t)m * SS_ + iE) * SS_ + jc;
                size_t base1 = base0 + (size_t)8 * SS_ * SS_;
                float2 p0 = *(float2*)(g_sc + base0);
                float2 p1 = *(float2*)(g_sc + base1);
                p0.x += acc[mi][ni][0] * SCALE; p0.y += acc[mi][ni][1] * SCALE;
                p1.x += acc[mi][ni][2] * SCALE; p1.y += acc[mi][ni][3] * SCALE;
                *(float2*)(g_sc + base0) = p0;
                *(float2*)(g_sc + base1) = p1;
            }
        }
    }
}

// ===========================================================================
// Softmax + split: read fp32 scores row, write wh/wl bf16
// ===========================================================================
__global__ __launch_bounds__(256) void k_softmax_split()
{
    const int warp = threadIdx.x >> 5, lane = threadIdx.x & 31;
    const size_t row = (size_t)blockIdx.x * 8 + warp;
    const float* p = g_sc + row * SS_;

    float4 v[4];
    float mx = -1e30f;
#pragma unroll
    for (int w = 0; w < 4; w++) {
        v[w] = *(const float4*)(p + w * 128 + lane * 4);
        mx = fmaxf(mx, fmaxf(fmaxf(v[w].x, v[w].y), fmaxf(v[w].z, v[w].w)));
    }
#pragma unroll
    for (int o = 16; o > 0; o >>= 1) mx = fmaxf(mx, __shfl_xor_sync(~0u, mx, o));

    float sum = 0.f;
#pragma unroll
    for (int w = 0; w < 4; w++) {
        v[w].x = __expf(v[w].x - mx); v[w].y = __expf(v[w].y - mx);
        v[w].z = __expf(v[w].z - mx); v[w].w = __expf(v[w].w - mx);
        sum += v[w].x + v[w].y + v[w].z + v[w].w;
    }
#pragma unroll
    for (int o = 16; o > 0; o >>= 1) sum += __shfl_xor_sync(~0u, sum, o);
    float r = 1.f / sum;
#pragma unroll
    for (int w = 0; w < 4; w++) {
        float f[4] = {v[w].x * r, v[w].y * r, v[w].z * r, v[w].w * r};
        uint32_t hu[2], lu[2];
#pragma unroll
        for (int pq = 0; pq < 2; pq++) {
            __nv_bfloat16 h0 = __float2bfloat16(f[2*pq]);
            __nv_bfloat16 h1 = __float2bfloat16(f[2*pq+1]);
            __nv_bfloat16 l0 = __float2bfloat16(f[2*pq]   - __bfloat162float(h0));
            __nv_bfloat16 l1 = __float2bfloat16(f[2*pq+1] - __bfloat162float(h1));
            hu[pq] = pk2(h0, h1); lu[pq] = pk2(l0, l1);
        }
        size_t off = row * SS_ + w * 128 + lane * 4;
        *(uint2*)(wh + off) = make_uint2(hu[0], hu[1]);
        *(uint2*)(wl + off) = make_uint2(lu[0], lu[1]);
    }
}

// ===========================================================================
// Context GEMM (3-term bf16, 128x64 CTA, 48 chunks of 32, 3-stage pipeline)
// mode 0 (content): grid(4 it, 128 bh): g_ctx = acc
// mode 1 (edge):    grid(512 i):        g_ctx += acc
// ===========================================================================
#define CT_A_TILEB (128 * LDS_ * 2)   // 10240
#define CT_B_TILEB (64 * LDS_ * 2)    // 5120
#define CT_STAGE   (CT_A_TILEB + CT_B_TILEB)

__global__ __launch_bounds__(256) void k_ctx(int mode)
{
    __shared__ __align__(16) char smem[3 * CT_STAGE];   // 46080 B
    const int tid = threadIdx.x, wid = tid >> 5, lane = tid & 31;
    const int wm = wid >> 1, wn = wid & 1;

    const __nv_bfloat16 *A0, *A1, *B0, *B1;
    size_t rsA;
    int i0 = 0, bh = 0, iE = 0;
    if (mode == 0) {
        bh = blockIdx.y; i0 = blockIdx.x * 128;
        A0 = wh + (size_t)bh * SS_ * SS_ + (size_t)i0 * SS_;
        A1 = wl + (size_t)bh * SS_ * SS_ + (size_t)i0 * SS_;
        B0 = vth + (size_t)bh * DKV * SS_;
        B1 = vtl + (size_t)bh * DKV * SS_;
        rsA = SS_;
    } else {
        iE = blockIdx.x;
        A0 = wh + (size_t)iE * SS_;
        A1 = wl + (size_t)iE * SS_;
        B0 = evth + (size_t)iE * DKV * SS_;
        B1 = evtl + (size_t)iE * DKV * SS_;
        rsA = (size_t)SS_ * SS_;
    }
    const __nv_bfloat16* At[3] = {A0, A0, A1};
    const __nv_bfloat16* Bt[3] = {B0, B1, B0};

    const uint32_t sbase = s2u(smem);
    const int arow = tid >> 1, aseg = (tid & 1) << 4;
    const int brow = tid >> 2, bseg = (tid & 3) << 3;

    float acc[2][4][4];
#pragma unroll
    for (int i = 0; i < 2; i++)
#pragma unroll
        for (int j = 0; j < 4; j++)
#pragma unroll
            for (int q = 0; q < 4; q++) acc[i][j][q] = 0.f;

#pragma unroll
    for (int pc = 0; pc < 2; pc++) {
        uint32_t dA = sbase + pc * CT_STAGE, dB = dA + CT_A_TILEB;
        int t2 = pc >> 4, ko2 = (pc & 15) * 32;
        CP_ASYNC16(dA + (arow * LDS_ + aseg) * 2,     At[t2] + (size_t)arow * rsA + ko2 + aseg);
        CP_ASYNC16(dA + (arow * LDS_ + aseg + 8) * 2, At[t2] + (size_t)arow * rsA + ko2 + aseg + 8);
        CP_ASYNC16(dB + (brow * LDS_ + bseg) * 2,     Bt[t2] + (size_t)brow * SS_ + ko2 + bseg);
        CP_COMMIT();
    }

    for (int c = 0; c < 48; c++) {
        if (c + 1 < 48) CP_WAIT1(); else CP_WAIT0();
        __syncthreads();

        if (c + 2 < 48) {
            int t2 = (c + 2) >> 4, ko2 = ((c + 2) & 15) * 32;
            uint32_t dA = sbase + ((c + 2) % 3) * CT_STAGE;
            uint32_t dB = dA + CT_A_TILEB;
            CP_ASYNC16(dA + (arow * LDS_ + aseg) * 2,     At[t2] + (size_t)arow * rsA + ko2 + aseg);
            CP_ASYNC16(dA + (arow * LDS_ + aseg + 8) * 2, At[t2] + (size_t)arow * rsA + ko2 + aseg + 8);
            CP_ASYNC16(dB + (brow * LDS_ + bseg) * 2,     Bt[t2] + (size_t)brow * SS_ + ko2 + bseg);
            CP_COMMIT();
        }

        const uint32_t bufA = sbase + (c % 3) * CT_STAGE;
        const uint32_t bufB = bufA + CT_A_TILEB;
        const int lr = lane & 15, lc = (lane >> 4) << 3;

#pragma unroll
        for (int ks = 0; ks < 2; ks++) {
            uint32_t a[2][4];
#pragma unroll
            for (int mi = 0; mi < 2; mi++) {
                uint32_t addr = bufA + ((wm * 32 + mi * 16 + lr) * LDS_ + ks * 16 + lc) * 2;
                LDMATX4(a[mi][0], a[mi][1], a[mi][2], a[mi][3], addr);
            }
            uint32_t b[4][2];
#pragma unroll
            for (int ni2 = 0; ni2 < 2; ni2++) {
                uint32_t r0, r1, r2, r3;
                uint32_t addr = bufB + ((wn * 32 + ni2 * 16 + lr) * LDS_ + ks * 16 + lc) * 2;
                LDMATX4(r0, r1, r2, r3, addr);
                b[2 * ni2][0] = r0;     b[2 * ni2][1] = r2;
                b[2 * ni2 + 1][0] = r1; b[2 * ni2 + 1][1] = r3;
            }
#pragma unroll
            for (int mi = 0; mi < 2; mi++)
#pragma unroll
                for (int ni = 0; ni < 4; ni++)
                    MMA16816(acc[mi][ni], a[mi], b[ni]);
        }
    }

    const int g = lane >> 2, tc = (lane & 3) << 1;
#pragma unroll
    for (int mi = 0; mi < 2; mi++) {
        int m = wm * 32 + mi * 16 + g;
#pragma unroll
        for (int ni = 0; ni < 4; ni++) {
            int ncol = wn * 32 + ni * 8 + tc;
            if (mode == 0) {
                int i = i0 + m;
                size_t a0 = ((size_t)(bh >> 4) * SS_ + i) * DM + (bh & 15) * DKV + ncol;
                size_t a1 = a0 + (size_t)8 * DM;
                float2 o0 = {acc[mi][ni][0], acc[mi][ni][1]};
                float2 o1 = {acc[mi][ni][2], acc[mi][ni][3]};
                *(float2*)(g_ctx + a0) = o0;
                *(float2*)(g_ctx + a1) = o1;
            } else {
                int bh0 = m, bh1 = m + 8;
                size_t a0 = ((size_t)(bh0 >> 4) * SS_ + iE) * DM + (bh0 & 15) * DKV + ncol;
                size_t a1 = ((size_t)(bh1 >> 4) * SS_ + iE) * DM + (bh1 & 15) * DKV + ncol;
                float2 p0 = *(float2*)(g_ctx + a0);
                float2 p1 = *(float2*)(g_ctx + a1);
                p0.x += acc[mi][ni][0]; p0.y += acc[mi][ni][1];
                p1.x += acc[mi][ni][2]; p1.y += acc[mi][ni][3];
                *(float2*)(g_ctx + a0) = p0;
                *(float2*)(g_ctx + a1) = p1;
            }
        }
    }
}

// ===========================================================================
// Launcher — fork edge splits onto a side stream, join before edge scores.
// ===========================================================================
extern "C" void kernel_launch(void* const* d_in, const int* in_sizes, int n_in,
                              void* d_out, int out_size)
{
    const float* queries     = (const float*)d_in[0];
    const float* edges_key   = (const float*)d_in[1];
    const float* edges_value = (const float*)d_in[2];
    const float* attn_bias   = (const float*)d_in[3];
    const float* Wq = (const float*)d_in[4];
    const float* bq = (const float*)d_in[5];
    const float* Wk = (const float*)d_in[6];
    const float* bk = (const float*)d_in[7];
    const float* Wv = (const float*)d_in[8];
    const float* bv = (const float*)d_in[9];
    const float* Wo = (const float*)d_in[10];
    const float* bo = (const float*)d_in[11];
    float* out = (float*)d_out;

    static cudaStream_t s2 = nullptr;
    static cudaEvent_t evFork = nullptr, evJoin = nullptr;
    static bool attrSet = false;
    if (!s2) {
        cudaStreamCreateWithFlags(&s2, cudaStreamNonBlocking);
        cudaEventCreateWithFlags(&evFork, cudaEventDisableTiming);
        cudaEventCreateWithFlags(&evJoin, cudaEventDisableTiming);
    }
    if (!attrSet) {
        cudaFuncSetAttribute(k_gemm_bf16, cudaFuncAttributeMaxDynamicSharedMemorySize, GSMEM);
        cudaFuncSetAttribute(k_scores,    cudaFuncAttributeMaxDynamicSharedMemorySize, GSMEM);
        attrSet = true;
    }

    cudaStream_t st = 0;
    cudaStreamCaptureStatus cs = cudaStreamCaptureStatusNone;
    if (cudaStreamIsCapturing(cudaStreamPerThread, &cs) == cudaSuccess &&
        cs == cudaStreamCaptureStatusActive)
        st = cudaStreamPerThread;

    // fork: edge-tensor splits run concurrently with projection path
    cudaEventRecord(evFork, st);
    cudaStreamWaitEvent(s2, evFork, 0);
    k_split_ek <<<8192, 256, 0, s2>>>(edges_key);
    k_split_evt<<<dim3(16, 2, 512), 256, 0, s2>>>(edges_value);
    cudaEventRecord(evJoin, s2);

    // projection path (main stream)
    k_split <<<2048, 256, 0, st>>>(queries, 0);
    k_wsplit<<<dim3(4, 128, 4), 256, 0, st>>>(Wq, Wk, Wv, Wo);
    k_gemm_bf16<<<dim3(24, 32), 256, GSMEM, st>>>(bq, bk, bv, nullptr, 0);

    // content scores (doesn't need edge splits)
    k_scores<<<dim3(4, 4, 128), 256, GSMEM, st>>>(attn_bias, 0);

    // join: edge splits must be complete before edge scores / edge context
    cudaStreamWaitEvent(st, evJoin, 0);
    k_scores<<<dim3(4, 512), 256, GSMEM, st>>>(nullptr, 1);

    // softmax -> bf16 split weights
    k_softmax_split<<<8192, 256, 0, st>>>();

    // context: content (write), then edge (accumulate)
    k_ctx<<<dim3(4, 128), 256, 0, st>>>(0);
    k_ctx<<<dim3(512),    256, 0, st>>>(1);

    // output projection
    k_split<<<2048, 256, 0, st>>>(nullptr, 1);
    k_gemm_bf16<<<dim3(8, 32), 256, GSMEM, st>>>(bo, nullptr, nullptr, out, 1);
}

// round 7
// speedup vs baseline: 1.7229x; 1.0934x over previous
#include <cuda_runtime.h>
#include <cuda_bf16.h>
#include <cstdint>

// ---------------------------------------------------------------------------
// Problem constants: B=8, S=512, D_MODEL=1024, H=16, DK=DV=64, BH=128
// ---------------------------------------------------------------------------
#define BB   8
#define SS_  512
#define DM   1024
#define HH   16
#define DKV  64
#define BH   128
#define SCALE 0.125f

// ---------------------------------------------------------------------------
// Scratch (device globals)
// ---------------------------------------------------------------------------
__device__ float g_sc  [(size_t)BH * SS_ * SS_];   // content scores + bias
__device__ float g_sc2 [(size_t)BH * SS_ * SS_];   // edge scores (separate!)
__device__ float g_ctx [(size_t)BB * SS_ * DM];    // content context
__device__ float g_ctx2[(size_t)BB * SS_ * DM];    // edge context (separate!)

// projection staging (3-term replicated layout)
__device__ __align__(16) __nv_bfloat16 g_A   [(size_t)4096 * 3072];
__device__ __align__(16) __nv_bfloat16 g_Actx[(size_t)4096 * 3072];
__device__ __align__(16) __nv_bfloat16 g_Bqkv[(size_t)3072 * 3072];
__device__ __align__(16) __nv_bfloat16 g_Bo  [(size_t)1024 * 3072];

// attention operand splits (hi/lo bf16)
__device__ __align__(16) __nv_bfloat16 qh [(size_t)BH * SS_ * DKV];
__device__ __align__(16) __nv_bfloat16 ql [(size_t)BH * SS_ * DKV];
__device__ __align__(16) __nv_bfloat16 kh [(size_t)BH * SS_ * DKV];
__device__ __align__(16) __nv_bfloat16 kl [(size_t)BH * SS_ * DKV];
__device__ __align__(16) __nv_bfloat16 vth[(size_t)BH * DKV * SS_];  // [bh,d,s]
__device__ __align__(16) __nv_bfloat16 vtl[(size_t)BH * DKV * SS_];
__device__ __align__(16) __nv_bfloat16 ekh [(size_t)SS_ * SS_ * DKV]; // [i,j,d]
__device__ __align__(16) __nv_bfloat16 ekl [(size_t)SS_ * SS_ * DKV];
__device__ __align__(16) __nv_bfloat16 evth[(size_t)SS_ * DKV * SS_]; // [i,d,j]
__device__ __align__(16) __nv_bfloat16 evtl[(size_t)SS_ * DKV * SS_];
__device__ __align__(16) __nv_bfloat16 wh [(size_t)BH * SS_ * SS_];   // [bh,i,j]
__device__ __align__(16) __nv_bfloat16 wl [(size_t)BH * SS_ * SS_];

__device__ __forceinline__ uint32_t s2u(const void* p) {
    uint32_t a;
    asm("{ .reg .u64 t; cvta.to.shared.u64 t, %1; cvt.u32.u64 %0, t; }"
        : "=r"(a) : "l"(p));
    return a;
}
__device__ __forceinline__ uint32_t pk2(__nv_bfloat16 a, __nv_bfloat16 b) {
    return (uint32_t)__bfloat16_as_ushort(a) | ((uint32_t)__bfloat16_as_ushort(b) << 16);
}

#define CP_ASYNC16(dst, src) \
    asm volatile("cp.async.cg.shared.global [%0], [%1], 16;" :: "r"(dst), "l"(src) : "memory")
#define CP_COMMIT() asm volatile("cp.async.commit_group;" ::: "memory")
#define CP_WAIT0()  asm volatile("cp.async.wait_group 0;" ::: "memory")

#define LDMATX4(r0, r1, r2, r3, addr) \
    asm volatile("ldmatrix.sync.aligned.m8n8.x4.shared.b16 {%0,%1,%2,%3}, [%4];" \
        : "=r"(r0), "=r"(r1), "=r"(r2), "=r"(r3) : "r"(addr))

#define MMA16816(c, a, b) \
    asm volatile("mma.sync.aligned.m16n8k16.row.col.f32.bf16.bf16.f32 " \
        "{%0,%1,%2,%3}, {%4,%5,%6,%7}, {%8,%9}, {%0,%1,%2,%3};" \
        : "+f"((c)[0]), "+f"((c)[1]), "+f"((c)[2]), "+f"((c)[3]) \
        : "r"((a)[0]), "r"((a)[1]), "r"((a)[2]), "r"((a)[3]), \
          "r"((b)[0]), "r"((b)[1]))

#define LDS_   40                 // padded row stride in bf16 (80 bytes)
#define TILEB  (128 * LDS_ * 2)   // 10240 bytes

// ===========================================================================
// Split conversion: fp32 [4096,1024] -> bf16 split [4096,3072]
// which=0: src=queries -> g_A ; which=1: src=g_ctx+g_ctx2 -> g_Actx
// ===========================================================================
__global__ __launch_bounds__(256) void k_split(const float* __restrict__ src_in, int which)
{
    int idx = blockIdx.x * 256 + threadIdx.x;
    int r = idx >> 7;
    int c0 = (idx & 127) << 3;
    float f[8];
    if (which == 0) {
        const float* s = src_in + (size_t)r * 1024 + c0;
        float4 v0 = *(const float4*)(s);
        float4 v1 = *(const float4*)(s + 4);
        f[0]=v0.x; f[1]=v0.y; f[2]=v0.z; f[3]=v0.w;
        f[4]=v1.x; f[5]=v1.y; f[6]=v1.z; f[7]=v1.w;
    } else {
        const float* s0 = (const float*)g_ctx  + (size_t)r * 1024 + c0;
        const float* s1 = (const float*)g_ctx2 + (size_t)r * 1024 + c0;
        float4 a0 = *(const float4*)(s0), a1 = *(const float4*)(s0 + 4);
        float4 b0 = *(const float4*)(s1), b1 = *(const float4*)(s1 + 4);
        f[0]=a0.x+b0.x; f[1]=a0.y+b0.y; f[2]=a0.z+b0.z; f[3]=a0.w+b0.w;
        f[4]=a1.x+b1.x; f[5]=a1.y+b1.y; f[6]=a1.z+b1.z; f[7]=a1.w+b1.w;
    }
    __nv_bfloat16* dst = which ? g_Actx : g_A;
    uint4 H, L;
    uint32_t hu[4], lu[4];
#pragma unroll
    for (int i = 0; i < 4; i++) {
        __nv_bfloat16 h0 = __float2bfloat16(f[2*i]);
        __nv_bfloat16 h1 = __float2bfloat16(f[2*i+1]);
        __nv_bfloat16 l0 = __float2bfloat16(f[2*i]   - __bfloat162float(h0));
        __nv_bfloat16 l1 = __float2bfloat16(f[2*i+1] - __bfloat162float(h1));
        hu[i] = pk2(h0, h1); lu[i] = pk2(l0, l1);
    }
    H.x = hu[0]; H.y = hu[1]; H.z = hu[2]; H.w = hu[3];
    L.x = lu[0]; L.y = lu[1]; L.z = lu[2]; L.w = lu[3];
    __nv_bfloat16* row = dst + (size_t)r * 3072;
    *(uint4*)(row + c0)        = H;
    *(uint4*)(row + 1024 + c0) = H;
    *(uint4*)(row + 2048 + c0) = L;
}

// ===========================================================================
// Weight split+transpose (4 weights, one launch): W[1024k,1024n]->B'[n][3072]
// ===========================================================================
__global__ __launch_bounds__(256) void k_wsplit(
    const float* __restrict__ W0, const float* __restrict__ W1,
    const float* __restrict__ W2, const float* __restrict__ W3)
{
    const int slot = blockIdx.z;
    const float* W = (slot == 0) ? W0 : (slot == 1) ? W1 : (slot == 2) ? W2 : W3;
    __nv_bfloat16* dst = (slot < 3) ? (g_Bqkv + (size_t)slot * 1024 * 3072) : g_Bo;
    int nl = blockIdx.x * 256 + threadIdx.x;
    int k0 = blockIdx.y << 3;
    uint4 H, L;
    uint32_t hu[4], lu[4];
#pragma unroll
    for (int i = 0; i < 4; i++) {
        float f0 = W[(size_t)(k0 + 2*i)     * 1024 + nl];
        float f1 = W[(size_t)(k0 + 2*i + 1) * 1024 + nl];
        __nv_bfloat16 h0 = __float2bfloat16(f0);
        __nv_bfloat16 h1 = __float2bfloat16(f1);
        __nv_bfloat16 l0 = __float2bfloat16(f0 - __bfloat162float(h0));
        __nv_bfloat16 l1 = __float2bfloat16(f1 - __bfloat162float(h1));
        hu[i] = pk2(h0, h1); lu[i] = pk2(l0, l1);
    }
    H.x = hu[0]; H.y = hu[1]; H.z = hu[2]; H.w = hu[3];
    L.x = lu[0]; L.y = lu[1]; L.z = lu[2]; L.w = lu[3];
    __nv_bfloat16* row = dst + (size_t)nl * 3072;
    *(uint4*)(row + k0)        = H;
    *(uint4*)(row + 1024 + k0) = L;
    *(uint4*)(row + 2048 + k0) = H;
}

// ===========================================================================
// EK split: fp32 [i,j,64] -> ekh/ekl bf16 (elementwise)
// ===========================================================================
__global__ __launch_bounds__(256) void k_split_ek(const float* __restrict__ EK)
{
    size_t base = ((size_t)blockIdx.x * 256 + threadIdx.x) * 8;
    float4 v0 = *(const float4*)(EK + base);
    float4 v1 = *(const float4*)(EK + base + 4);
    float f[8] = {v0.x, v0.y, v0.z, v0.w, v1.x, v1.y, v1.z, v1.w};
    uint4 H, L;
    uint32_t hu[4], lu[4];
#pragma unroll
    for (int i = 0; i < 4; i++) {
        __nv_bfloat16 h0 = __float2bfloat16(f[2*i]);
        __nv_bfloat16 h1 = __float2bfloat16(f[2*i+1]);
        __nv_bfloat16 l0 = __float2bfloat16(f[2*i]   - __bfloat162float(h0));
        __nv_bfloat16 l1 = __float2bfloat16(f[2*i+1] - __bfloat162float(h1));
        hu[i] = pk2(h0, h1); lu[i] = pk2(l0, l1);
    }
    H.x = hu[0]; H.y = hu[1]; H.z = hu[2]; H.w = hu[3];
    L.x = lu[0]; L.y = lu[1]; L.z = lu[2]; L.w = lu[3];
    *(uint4*)(ekh + base) = H;
    *(uint4*)(ekl + base) = L;
}

// ===========================================================================
// EV transpose-split: fp32 [i,j,64] -> evth/evtl bf16 [i,64,512]
// ===========================================================================
__global__ __launch_bounds__(256) void k_split_evt(const float* __restrict__ EV)
{
    __shared__ float ts[32][33];
    const int jt = blockIdx.x, dt = blockIdx.y, i = blockIdx.z;
    const int t = threadIdx.x;
    const int r = t >> 3, c0 = (t & 7) << 2;

    float4 v = *(const float4*)(EV + ((size_t)(i * SS_ + jt * 32 + r)) * DKV + dt * 32 + c0);
    ts[r][c0 + 0] = v.x; ts[r][c0 + 1] = v.y;
    ts[r][c0 + 2] = v.z; ts[r][c0 + 3] = v.w;
    __syncthreads();

    uint32_t hu[2], lu[2];
#pragma unroll
    for (int p = 0; p < 2; p++) {
        float f0 = ts[c0 + 2*p][r];
        float f1 = ts[c0 + 2*p + 1][r];
        __nv_bfloat16 h0 = __float2bfloat16(f0);
        __nv_bfloat16 h1 = __float2bfloat16(f1);
        __nv_bfloat16 l0 = __float2bfloat16(f0 - __bfloat162float(h0));
        __nv_bfloat16 l1 = __float2bfloat16(f1 - __bfloat162float(h1));
        hu[p] = pk2(h0, h1); lu[p] = pk2(l0, l1);
    }
    size_t off = ((size_t)i * DKV + dt * 32 + r) * SS_ + jt * 32 + c0;
    *(uint2*)(evth + off) = make_uint2(hu[0], hu[1]);
    *(uint2*)(evtl + off) = make_uint2(lu[0], lu[1]);
}

// ===========================================================================
// bf16 mma.sync GEMM (projections): C[4096,N] = A'[4096,3072] @ B'[N,3072]^T
// 128x128 CTA, 8 warps 64x32, BK=32, 2-stage cp.async (R4 body).
// mode 0: QKV -> q/k splits + transposed-v splits; mode 1: OUT -> outp
// ===========================================================================
#define KTOT   3072
#define NCHUNK 96

__global__ __launch_bounds__(256) void k_gemm_bf16(
    const float* __restrict__ b0p, const float* __restrict__ b1p,
    const float* __restrict__ b2p, float* __restrict__ outp, int mode)
{
    __shared__ __align__(16) char smem[2 * 2 * TILEB];

    const int tid  = threadIdx.x;
    const int wid  = tid >> 5, lane = tid & 31;
    const int wm   = wid >> 2, wn = wid & 3;
    const int m0   = blockIdx.y * 128, n0 = blockIdx.x * 128;
    const uint32_t sbase = s2u(smem);

    const __nv_bfloat16* __restrict__ Ag = mode ? g_Actx : g_A;
    const __nv_bfloat16* __restrict__ Bg = mode ? g_Bo   : g_Bqkv;

    const int lrow0 = tid >> 2;
    const int lseg  = (tid & 3) << 3;

    float acc[4][4][4];
#pragma unroll
    for (int i = 0; i < 4; i++)
#pragma unroll
        for (int j = 0; j < 4; j++)
#pragma unroll
            for (int q = 0; q < 4; q++) acc[i][j][q] = 0.f;

    {
        uint32_t dA = sbase, dB = sbase + TILEB;
#pragma unroll
        for (int u = 0; u < 2; u++) {
            int row = lrow0 + u * 64;
            CP_ASYNC16(dA + (row * LDS_ + lseg) * 2, Ag + (size_t)(m0 + row) * KTOT + lseg);
            CP_ASYNC16(dB + (row * LDS_ + lseg) * 2, Bg + (size_t)(n0 + row) * KTOT + lseg);
        }
        CP_COMMIT();
    }

    for (int c = 0; c < NCHUNK; c++) {
        CP_WAIT0();
        __syncthreads();

        if (c + 1 < NCHUNK) {
            uint32_t dA = sbase + ((c + 1) & 1) * 2 * TILEB;
            uint32_t dB = dA + TILEB;
            const int koff = (c + 1) * 32 + lseg;
#pragma unroll
            for (int u = 0; u < 2; u++) {
                int row = lrow0 + u * 64;
                CP_ASYNC16(dA + (row * LDS_ + lseg) * 2, Ag + (size_t)(m0 + row) * KTOT + koff);
                CP_ASYNC16(dB + (row * LDS_ + lseg) * 2, Bg + (size_t)(n0 + row) * KTOT + koff);
            }
            CP_COMMIT();
        }

        const uint32_t bufA = sbase + (c & 1) * 2 * TILEB;
        const uint32_t bufB = bufA + TILEB;
        const int lr = lane & 15, lc = (lane >> 4) << 3;

#pragma unroll
        for (int ks = 0; ks < 2; ks++) {
            uint32_t a[4][4];
#pragma unroll
            for (int mi = 0; mi < 4; mi++) {
                uint32_t addr = bufA + ((wm * 64 + mi * 16 + lr) * LDS_ + ks * 16 + lc) * 2;
                LDMATX4(a[mi][0], a[mi][1], a[mi][2], a[mi][3], addr);
            }
            uint32_t b[4][2];
#pragma unroll
            for (int ni2 = 0; ni2 < 2; ni2++) {
                uint32_t r0, r1, r2, r3;
                uint32_t addr = bufB + ((wn * 32 + ni2 * 16 + lr) * LDS_ + ks * 16 + lc) * 2;
                LDMATX4(r0, r1, r2, r3, addr);
                b[2 * ni2][0] = r0;     b[2 * ni2][1] = r2;
                b[2 * ni2 + 1][0] = r1; b[2 * ni2 + 1][1] = r3;
            }
#pragma unroll
            for (int mi = 0; mi < 4; mi++)
#pragma unroll
                for (int ni = 0; ni < 4; ni++)
                    MMA16816(acc[mi][ni], a[mi], b[ni]);
        }
        __syncthreads();
    }

    // -------- epilogue --------
    const int g  = lane >> 2;
    const int tc = (lane & 3) << 1;

    if (mode == 0) {
        const int proj = n0 >> 10;
        const float* bias = (proj == 0) ? b0p : (proj == 1) ? b1p : b2p;
#pragma unroll
        for (int mi = 0; mi < 4; mi++) {
            int m = m0 + wm * 64 + mi * 16 + g;
            int b_ = m >> 9, s_ = m & 511;
            int s2 = s_ + 8;
#pragma unroll
            for (int ni = 0; ni < 4; ni++) {
                int nl = (n0 & 1023) + wn * 32 + ni * 8 + tc;
                int hd = nl >> 6, d = nl & 63;
                int bh_ = b_ * HH + hd;
                float x0 = acc[mi][ni][0] + bias[nl];
                float x1 = acc[mi][ni][1] + bias[nl + 1];
                float x2 = acc[mi][ni][2] + bias[nl];
                float x3 = acc[mi][ni][3] + bias[nl + 1];
                __nv_bfloat16 hb0 = __float2bfloat16(x0), lb0 = __float2bfloat16(x0 - __bfloat162float(hb0));
                __nv_bfloat16 hb1 = __float2bfloat16(x1), lb1 = __float2bfloat16(x1 - __bfloat162float(hb1));
                __nv_bfloat16 hb2 = __float2bfloat16(x2), lb2 = __float2bfloat16(x2 - __bfloat162float(hb2));
                __nv_bfloat16 hb3 = __float2bfloat16(x3), lb3 = __float2bfloat16(x3 - __bfloat162float(hb3));
                if (proj < 2) {
                    __nv_bfloat16* ah = (proj == 0) ? qh : kh;
                    __nv_bfloat16* al = (proj == 0) ? ql : kl;
                    size_t o0 = ((size_t)bh_ * SS_ + s_) * DKV + d;
                    size_t o1 = o0 + 8 * DKV;
                    *(uint32_t*)(ah + o0) = pk2(hb0, hb1);
                    *(uint32_t*)(al + o0) = pk2(lb0, lb1);
                    *(uint32_t*)(ah + o1) = pk2(hb2, hb3);
                    *(uint32_t*)(al + o1) = pk2(lb2, lb3);
                } else {
                    size_t o = (size_t)bh_ * DKV * SS_ + (size_t)d * SS_;
                    vth[o + s_]       = hb0;  vtl[o + s_]       = lb0;
                    vth[o + SS_ + s_] = hb1;  vtl[o + SS_ + s_] = lb1;
                    vth[o + s2]       = hb2;  vtl[o + s2]       = lb2;
                    vth[o + SS_ + s2] = hb3;  vtl[o + SS_ + s2] = lb3;
                }
            }
        }
    } else {
#pragma unroll
        for (int mi = 0; mi < 4; mi++) {
            int m = m0 + wm * 64 + mi * 16 + g;
#pragma unroll
            for (int ni = 0; ni < 4; ni++) {
                int ncol = n0 + wn * 32 + ni * 8 + tc;
                float2 o0 = {acc[mi][ni][0] + b0p[ncol],
                             acc[mi][ni][1] + b0p[ncol + 1]};
                float2 o1 = {acc[mi][ni][2] + b0p[ncol],
                             acc[mi][ni][3] + b0p[ncol + 1]};
                *(float2*)(outp + (size_t)m * DM + ncol) = o0;
                *(float2*)(outp + (size_t)(m + 8) * DM + ncol) = o1;
            }
        }
    }
}

// ===========================================================================
// Scores GEMM (3-term bf16, 128x128 CTA, 6 chunks of 32, 2-stage)
// mode 0 (content): grid(4 jt, 4 it, 128 bh): g_sc  = acc*SCALE + bias
// mode 1 (edge):    grid(4 jt, 512 i):        g_sc2 = acc*SCALE   (pure write)
// ===========================================================================
__global__ __launch_bounds__(256) void k_scores(const float* __restrict__ bias, int mode)
{
    __shared__ __align__(16) char smem[2 * 2 * TILEB];
    const int tid = threadIdx.x, wid = tid >> 5, lane = tid & 31;
    const int wm = wid >> 2, wn = wid & 3;
    const int j0 = blockIdx.x * 128;

    const __nv_bfloat16 *A0, *A1, *B0, *B1;
    size_t rsA;
    int i0 = 0, bh = 0, iE = 0;
    if (mode == 0) {
        i0 = blockIdx.y * 128; bh = blockIdx.z;
        A0 = qh + ((size_t)bh * SS_ + i0) * DKV;
        A1 = ql + ((size_t)bh * SS_ + i0) * DKV;
        B0 = kh + ((size_t)bh * SS_ + j0) * DKV;
        B1 = kl + ((size_t)bh * SS_ + j0) * DKV;
        rsA = DKV;
    } else {
        iE = blockIdx.y;
        A0 = qh + (size_t)iE * DKV;
        A1 = ql + (size_t)iE * DKV;
        B0 = ekh + ((size_t)iE * SS_ + j0) * DKV;
        B1 = ekl + ((size_t)iE * SS_ + j0) * DKV;
        rsA = (size_t)SS_ * DKV;
    }
    const __nv_bfloat16* At[3] = {A0, A0, A1};
    const __nv_bfloat16* Bt[3] = {B0, B1, B0};

    const uint32_t sbase = s2u(smem);
    const int lrow0 = tid >> 2, lseg = (tid & 3) << 3;

    float acc[4][4][4];
#pragma unroll
    for (int i = 0; i < 4; i++)
#pragma unroll
        for (int j = 0; j < 4; j++)
#pragma unroll
            for (int q = 0; q < 4; q++) acc[i][j][q] = 0.f;

    {
        uint32_t dA = sbase, dB = sbase + TILEB;
#pragma unroll
        for (int u = 0; u < 2; u++) {
            int row = lrow0 + u * 64;
            CP_ASYNC16(dA + (row * LDS_ + lseg) * 2, At[0] + (size_t)row * rsA + lseg);
            CP_ASYNC16(dB + (row * LDS_ + lseg) * 2, Bt[0] + (size_t)row * DKV + lseg);
        }
        CP_COMMIT();
    }

    for (int c = 0; c < 6; c++) {
        CP_WAIT0();
        __syncthreads();

        if (c + 1 < 6) {
            int t2 = (c + 1) >> 1, ko2 = ((c + 1) & 1) * 32;
            uint32_t dA = sbase + ((c + 1) & 1) * 2 * TILEB;
            uint32_t dB = dA + TILEB;
#pragma unroll
            for (int u = 0; u < 2; u++) {
                int row = lrow0 + u * 64;
                CP_ASYNC16(dA + (row * LDS_ + lseg) * 2, At[t2] + (size_t)row * rsA + ko2 + lseg);
                CP_ASYNC16(dB + (row * LDS_ + lseg) * 2, Bt[t2] + (size_t)row * DKV + ko2 + lseg);
            }
            CP_COMMIT();
        }

        const uint32_t bufA = sbase + (c & 1) * 2 * TILEB;
        const uint32_t bufB = bufA + TILEB;
        const int lr = lane & 15, lc = (lane >> 4) << 3;

#pragma unroll
        for (int ks = 0; ks < 2; ks++) {
            uint32_t a[4][4];
#pragma unroll
            for (int mi = 0; mi < 4; mi++) {
                uint32_t addr = bufA + ((wm * 64 + mi * 16 + lr) * LDS_ + ks * 16 + lc) * 2;
                LDMATX4(a[mi][0], a[mi][1], a[mi][2], a[mi][3], addr);
            }
            uint32_t b[4][2];
#pragma unroll
            for (int ni2 = 0; ni2 < 2; ni2++) {
                uint32_t r0, r1, r2, r3;
                uint32_t addr = bufB + ((wn * 32 + ni2 * 16 + lr) * LDS_ + ks * 16 + lc) * 2;
                LDMATX4(r0, r1, r2, r3, addr);
                b[2 * ni2][0] = r0;     b[2 * ni2][1] = r2;
                b[2 * ni2 + 1][0] = r1; b[2 * ni2 + 1][1] = r3;
            }
#pragma unroll
            for (int mi = 0; mi < 4; mi++)
#pragma unroll
                for (int ni = 0; ni < 4; ni++)
                    MMA16816(acc[mi][ni], a[mi], b[ni]);
        }
        __syncthreads();
    }

    const int g = lane >> 2, tc = (lane & 3) << 1;
#pragma unroll
    for (int mi = 0; mi < 4; mi++) {
        int m = wm * 64 + mi * 16 + g;
#pragma unroll
        for (int ni = 0; ni < 4; ni++) {
            int jc = j0 + wn * 32 + ni * 8 + tc;
            if (mode == 0) {
                size_t base0 = ((size_t)bh * SS_ + (i0 + m)) * SS_ + jc;
                size_t base1 = base0 + 8 * SS_;
                float2 o0 = {acc[mi][ni][0] * SCALE + bias[base0],
                             acc[mi][ni][1] * SCALE + bias[base0 + 1]};
                float2 o1 = {acc[mi][ni][2] * SCALE + bias[base1],
                             acc[mi][ni][3] * SCALE + bias[base1 + 1]};
                *(float2*)(g_sc + base0) = o0;
                *(float2*)(g_sc + base1) = o1;
            } else {
                size_t base0 = ((size_t)m * SS_ + iE) * SS_ + jc;
                size_t base1 = base0 + (size_t)8 * SS_ * SS_;
                float2 o0 = {acc[mi][ni][0] * SCALE, acc[mi][ni][1] * SCALE};
                float2 o1 = {acc[mi][ni][2] * SCALE, acc[mi][ni][3] * SCALE};
                *(float2*)(g_sc2 + base0) = o0;
                *(float2*)(g_sc2 + base1) = o1;
            }
        }
    }
}

// ===========================================================================
// Softmax + split: read g_sc + g_sc2, softmax, write wh/wl bf16
// ===========================================================================
__global__ __launch_bounds__(256) void k_softmax_split()
{
    const int warp = threadIdx.x >> 5, lane = threadIdx.x & 31;
    const size_t row = (size_t)blockIdx.x * 8 + warp;
    const float* p  = g_sc  + row * SS_;
    const float* p2 = g_sc2 + row * SS_;

    float4 v[4];
    float mx = -1e30f;
#pragma unroll
    for (int w = 0; w < 4; w++) {
        float4 a = *(const float4*)(p  + w * 128 + lane * 4);
        float4 b = *(const float4*)(p2 + w * 128 + lane * 4);
        v[w].x = a.x + b.x; v[w].y = a.y + b.y;
        v[w].z = a.z + b.z; v[w].w = a.w + b.w;
        mx = fmaxf(mx, fmaxf(fmaxf(v[w].x, v[w].y), fmaxf(v[w].z, v[w].w)));
    }
#pragma unroll
    for (int o = 16; o > 0; o >>= 1) mx = fmaxf(mx, __shfl_xor_sync(~0u, mx, o));

    float sum = 0.f;
#pragma unroll
    for (int w = 0; w < 4; w++) {
        v[w].x = __expf(v[w].x - mx); v[w].y = __expf(v[w].y - mx);
        v[w].z = __expf(v[w].z - mx); v[w].w = __expf(v[w].w - mx);
        sum += v[w].x + v[w].y + v[w].z + v[w].w;
    }
#pragma unroll
    for (int o = 16; o > 0; o >>= 1) sum += __shfl_xor_sync(~0u, sum, o);
    float r = 1.f / sum;
#pragma unroll
    for (int w = 0; w < 4; w++) {
        float f[4] = {v[w].x * r, v[w].y * r, v[w].z * r, v[w].w * r};
        uint32_t hu[2], lu[2];
#pragma unroll
        for (int pq = 0; pq < 2; pq++) {
            __nv_bfloat16 h0 = __float2bfloat16(f[2*pq]);
            __nv_bfloat16 h1 = __float2bfloat16(f[2*pq+1]);
            __nv_bfloat16 l0 = __float2bfloat16(f[2*pq]   - __bfloat162float(h0));
            __nv_bfloat16 l1 = __float2bfloat16(f[2*pq+1] - __bfloat162float(h1));
            hu[pq] = pk2(h0, h1); lu[pq] = pk2(l0, l1);
        }
        size_t off = row * SS_ + w * 128 + lane * 4;
        *(uint2*)(wh + off) = make_uint2(hu[0], hu[1]);
        *(uint2*)(wl + off) = make_uint2(lu[0], lu[1]);
    }
}

// ===========================================================================
// Context GEMM (3-term bf16, 128x64 CTA, 48 chunks of 32, 2-stage)
// mode 0 (content): grid(4 it, 128 bh): g_ctx  = acc
// mode 1 (edge):    grid(512 i):        g_ctx2 = acc   (pure write)
// ===========================================================================
#define CT_A_TILEB (128 * LDS_ * 2)
#define CT_B_TILEB (64 * LDS_ * 2)
#define CT_STAGE   (CT_A_TILEB + CT_B_TILEB)

__global__ __launch_bounds__(256) void k_ctx(int mode)
{
    __shared__ __align__(16) char smem[2 * CT_STAGE];
    const int tid = threadIdx.x, wid = tid >> 5, lane = tid & 31;
    const int wm = wid >> 1, wn = wid & 1;

    const __nv_bfloat16 *A0, *A1, *B0, *B1;
    size_t rsA;
    int i0 = 0, bh = 0, iE = 0;
    if (mode == 0) {
        bh = blockIdx.y; i0 = blockIdx.x * 128;
        A0 = wh + (size_t)bh * SS_ * SS_ + (size_t)i0 * SS_;
        A1 = wl + (size_t)bh * SS_ * SS_ + (size_t)i0 * SS_;
        B0 = vth + (size_t)bh * DKV * SS_;
        B1 = vtl + (size_t)bh * DKV * SS_;
        rsA = SS_;
    } else {
        iE = blockIdx.x;
        A0 = wh + (size_t)iE * SS_;
        A1 = wl + (size_t)iE * SS_;
        B0 = evth + (size_t)iE * DKV * SS_;
        B1 = evtl + (size_t)iE * DKV * SS_;
        rsA = (size_t)SS_ * SS_;
    }
    const __nv_bfloat16* At[3] = {A0, A0, A1};
    const __nv_bfloat16* Bt[3] = {B0, B1, B0};

    const uint32_t sbase = s2u(smem);
    const int arow = tid >> 1, aseg = (tid & 1) << 4;
    const int brow = tid >> 2, bseg = (tid & 3) << 3;

    float acc[2][4][4];
#pragma unroll
    for (int i = 0; i < 2; i++)
#pragma unroll
        for (int j = 0; j < 4; j++)
#pragma unroll
            for (int q = 0; q < 4; q++) acc[i][j][q] = 0.f;

    {
        uint32_t dA = sbase, dB = sbase + CT_A_TILEB;
        CP_ASYNC16(dA + (arow * LDS_ + aseg) * 2,     At[0] + (size_t)arow * rsA + aseg);
        CP_ASYNC16(dA + (arow * LDS_ + aseg + 8) * 2, At[0] + (size_t)arow * rsA + aseg + 8);
        CP_ASYNC16(dB + (brow * LDS_ + bseg) * 2,     Bt[0] + (size_t)brow * SS_ + bseg);
        CP_COMMIT();
    }

    for (int c = 0; c < 48; c++) {
        CP_WAIT0();
        __syncthreads();

        if (c + 1 < 48) {
            int t2 = (c + 1) >> 4, ko2 = ((c + 1) & 15) * 32;
            uint32_t dA = sbase + ((c + 1) & 1) * CT_STAGE;
            uint32_t dB = dA + CT_A_TILEB;
            CP_ASYNC16(dA + (arow * LDS_ + aseg) * 2,     At[t2] + (size_t)arow * rsA + ko2 + aseg);
            CP_ASYNC16(dA + (arow * LDS_ + aseg + 8) * 2, At[t2] + (size_t)arow * rsA + ko2 + aseg + 8);
            CP_ASYNC16(dB + (brow * LDS_ + bseg) * 2,     Bt[t2] + (size_t)brow * SS_ + ko2 + bseg);
            CP_COMMIT();
        }

        const uint32_t bufA = sbase + (c & 1) * CT_STAGE;
        const uint32_t bufB = bufA + CT_A_TILEB;
        const int lr = lane & 15, lc = (lane >> 4) << 3;

#pragma unroll
        for (int ks = 0; ks < 2; ks++) {
            uint32_t a[2][4];
#pragma unroll
            for (int mi = 0; mi < 2; mi++) {
                uint32_t addr = bufA + ((wm * 32 + mi * 16 + lr) * LDS_ + ks * 16 + lc) * 2;
                LDMATX4(a[mi][0], a[mi][1], a[mi][2], a[mi][3], addr);
            }
            uint32_t b[4][2];
#pragma unroll
            for (int ni2 = 0; ni2 < 2; ni2++) {
                uint32_t r0, r1, r2, r3;
                uint32_t addr = bufB + ((wn * 32 + ni2 * 16 + lr) * LDS_ + ks * 16 + lc) * 2;
                LDMATX4(r0, r1, r2, r3, addr);
                b[2 * ni2][0] = r0;     b[2 * ni2][1] = r2;
                b[2 * ni2 + 1][0] = r1; b[2 * ni2 + 1][1] = r3;
            }
#pragma unroll
            for (int mi = 0; mi < 2; mi++)
#pragma unroll
                for (int ni = 0; ni < 4; ni++)
                    MMA16816(acc[mi][ni], a[mi], b[ni]);
        }
        __syncthreads();
    }

    const int g = lane >> 2, tc = (lane & 3) << 1;
#pragma unroll
    for (int mi = 0; mi < 2; mi++) {
        int m = wm * 32 + mi * 16 + g;
#pragma unroll
        for (int ni = 0; ni < 4; ni++) {
            int ncol = wn * 32 + ni * 8 + tc;
            if (mode == 0) {
                int i = i0 + m;
                size_t a0 = ((size_t)(bh >> 4) * SS_ + i) * DM + (bh & 15) * DKV + ncol;
                size_t a1 = a0 + (size_t)8 * DM;
                *(float2*)(g_ctx + a0) = make_float2(acc[mi][ni][0], acc[mi][ni][1]);
                *(float2*)(g_ctx + a1) = make_float2(acc[mi][ni][2], acc[mi][ni][3]);
            } else {
                int bh0 = m, bh1 = m + 8;
                size_t a0 = ((size_t)(bh0 >> 4) * SS_ + iE) * DM + (bh0 & 15) * DKV + ncol;
                size_t a1 = ((size_t)(bh1 >> 4) * SS_ + iE) * DM + (bh1 & 15) * DKV + ncol;
                *(float2*)(g_ctx2 + a0) = make_float2(acc[mi][ni][0], acc[mi][ni][1]);
                *(float2*)(g_ctx2 + a1) = make_float2(acc[mi][ni][2], acc[mi][ni][3]);
            }
        }
    }
}

// ===========================================================================
// Launcher — multi-stream: edge splits ∥ projections; content ∥ edge pairs.
// ===========================================================================
extern "C" void kernel_launch(void* const* d_in, const int* in_sizes, int n_in,
                              void* d_out, int out_size)
{
    const float* queries     = (const float*)d_in[0];
    const float* edges_key   = (const float*)d_in[1];
    const float* edges_value = (const float*)d_in[2];
    const float* attn_bias   = (const float*)d_in[3];
    const float* Wq = (const float*)d_in[4];
    const float* bq = (const float*)d_in[5];
    const float* Wk = (const float*)d_in[6];
    const float* bk = (const float*)d_in[7];
    const float* Wv = (const float*)d_in[8];
    const float* bv = (const float*)d_in[9];
    const float* Wo = (const float*)d_in[10];
    const float* bo = (const float*)d_in[11];
    float* out = (float*)d_out;

    static cudaStream_t s2 = nullptr, s3 = nullptr;
    static cudaEvent_t evFork = nullptr, evEdgeSplit = nullptr, evQKV = nullptr,
                       evEdgeSc = nullptr, evSM = nullptr, evCtx1 = nullptr;
    if (!s2) {
        cudaStreamCreateWithFlags(&s2, cudaStreamNonBlocking);
        cudaStreamCreateWithFlags(&s3, cudaStreamNonBlocking);
        cudaEventCreateWithFlags(&evFork,      cudaEventDisableTiming);
        cudaEventCreateWithFlags(&evEdgeSplit, cudaEventDisableTiming);
        cudaEventCreateWithFlags(&evQKV,       cudaEventDisableTiming);
        cudaEventCreateWithFlags(&evEdgeSc,    cudaEventDisableTiming);
        cudaEventCreateWithFlags(&evSM,        cudaEventDisableTiming);
        cudaEventCreateWithFlags(&evCtx1,      cudaEventDisableTiming);
    }

    cudaStream_t st = 0;
    cudaStreamCaptureStatus cs = cudaStreamCaptureStatusNone;
    if (cudaStreamIsCapturing(cudaStreamPerThread, &cs) == cudaSuccess &&
        cs == cudaStreamCaptureStatusActive)
        st = cudaStreamPerThread;

    // fork: edge-tensor splits overlap the projection path
    cudaEventRecord(evFork, st);
    cudaStreamWaitEvent(s2, evFork, 0);
    k_split_ek <<<8192, 256, 0, s2>>>(edges_key);
    k_split_evt<<<dim3(16, 2, 512), 256, 0, s2>>>(edges_value);
    cudaEventRecord(evEdgeSplit, s2);

    // projection path (main stream)
    k_split <<<2048, 256, 0, st>>>(queries, 0);
    k_wsplit<<<dim3(4, 128, 4), 256, 0, st>>>(Wq, Wk, Wv, Wo);
    k_gemm_bf16<<<dim3(24, 32), 256, 0, st>>>(bq, bk, bv, nullptr, 0);
    cudaEventRecord(evQKV, st);

    // content scores (st) ∥ edge scores (s3, independent buffer g_sc2)
    cudaStreamWaitEvent(s3, evQKV, 0);
    cudaStreamWaitEvent(s3, evEdgeSplit, 0);
    k_scores<<<dim3(4, 512), 256, 0, s3>>>(nullptr, 1);
    cudaEventRecord(evEdgeSc, s3);

    k_scores<<<dim3(4, 4, 128), 256, 0, st>>>(attn_bias, 0);

    // softmax needs both score buffers
    cudaStreamWaitEvent(st, evEdgeSc, 0);
    k_softmax_split<<<8192, 256, 0, st>>>();
    cudaEventRecord(evSM, st);

    // content context (st) ∥ edge context (s3, independent buffer g_ctx2)
    cudaStreamWaitEvent(s3, evSM, 0);
    k_ctx<<<dim3(512), 256, 0, s3>>>(1);
    cudaEventRecord(evCtx1, s3);

    k_ctx<<<dim3(4, 128), 256, 0, st>>>(0);

    // output projection (needs both context buffers)
    cudaStreamWaitEvent(st, evCtx1, 0);
    k_split<<<2048, 256, 0, st>>>(nullptr, 1);
    k_gemm_bf16<<<dim3(8, 32), 256, 0, st>>>(bo, nullptr, nullptr, out, 1);
}